// round 1
// baseline (speedup 1.0000x reference)
#include <cuda_runtime.h>
#include <math.h>

// Problem constants
#define TT   2048   // tokens
#define DM   2048   // d_model
#define NH   32     // query heads
#define NKV  8      // kv heads
#define HD   64     // head dim
#define GRP  4      // NH/NKV

// Scratch (device globals — no allocation allowed)
__device__ float g_Q[TT * DM];          // [t][h*64+d], RoPE'd, pre-scaled later in attn
__device__ float g_K[NKV * TT * HD];    // [kv][t][d], RoPE'd
__device__ float g_V[NKV * TT * HD];    // [kv][t][d]
__device__ float g_O[TT * DM];          // attention output [t][h*64+d]

// ---------------------------------------------------------------------------
// Tiled FP32 GEMM: C[M,N] = A[M,2048] @ B[2048,N]
// BM=BN=64, BK=16, 256 threads, 4x4 microtile per thread.
// MODE 0: plain store to C (used for output projection, A = g_O)
// MODE 1: RoPE epilogue, store to g_Q (row-major [t][h*64+d])
// MODE 2: RoPE epilogue, store to g_K ([kv][t][d])
// MODE 3: plain epilogue, store to g_V ([kv][t][d])
// ---------------------------------------------------------------------------
template <int MODE>
__global__ __launch_bounds__(256)
void gemm_kernel(const float* __restrict__ A, const float* __restrict__ B,
                 float* __restrict__ C, int N, const float* __restrict__ freqs)
{
    __shared__ __align__(16) float As[16][65];   // [k][m], +1 pad
    __shared__ __align__(16) float Bs[16][64];   // [k][n]

    const int bx = blockIdx.x, by = blockIdx.y;
    const int tid = threadIdx.x;
    const int tx = tid & 15, ty = tid >> 4;
    const int row0 = by * 64, col0 = bx * 64;

    // A-load mapping: each thread loads a float4 along K
    const int arow = tid >> 2;          // 0..63
    const int akc  = (tid & 3) * 4;     // k-offset 0,4,8,12
    // B-load mapping: each thread loads a float4 along N
    const int bkk  = tid >> 4;          // 0..15
    const int bj   = (tid & 15) * 4;

    const float* Ab = (MODE == 0) ? (const float*)g_O : A;
    const float* Aptr = Ab + (size_t)(row0 + arow) * DM + akc;
    const float* Bptr = B + (size_t)bkk * N + col0 + bj;

    float acc[4][4] = {};

    for (int k0 = 0; k0 < DM; k0 += 16) {
        float4 av = *(const float4*)(Aptr + k0);
        As[akc + 0][arow] = av.x;
        As[akc + 1][arow] = av.y;
        As[akc + 2][arow] = av.z;
        As[akc + 3][arow] = av.w;
        *(float4*)&Bs[bkk][bj] = *(const float4*)(Bptr + (size_t)k0 * N);
        __syncthreads();

#pragma unroll
        for (int kk = 0; kk < 16; kk++) {
            float a[4];
#pragma unroll
            for (int i = 0; i < 4; i++) a[i] = As[kk][ty * 4 + i];
            float4 bv = *(const float4*)&Bs[kk][tx * 4];
            float b[4] = {bv.x, bv.y, bv.z, bv.w};
#pragma unroll
            for (int i = 0; i < 4; i++)
#pragma unroll
                for (int j = 0; j < 4; j++)
                    acc[i][j] = fmaf(a[i], b[j], acc[i][j]);
        }
        __syncthreads();
    }

    // Epilogue
#pragma unroll
    for (int i = 0; i < 4; i++) {
        const int r = row0 + ty * 4 + i;   // token
        if (MODE == 0) {
#pragma unroll
            for (int j = 0; j < 4; j++) {
                const int c = col0 + tx * 4 + j;
                C[(size_t)r * N + c] = acc[i][j];
            }
        } else if (MODE == 3) {
#pragma unroll
            for (int j = 0; j < 4; j++) {
                const int c = col0 + tx * 4 + j;
                const int kv = c >> 6, d = c & 63;
                g_V[((size_t)kv * TT + r) * HD + d] = acc[i][j];
            }
        } else {
            // RoPE: pairs (even, odd) are adjacent columns; tx*4 is 4-aligned
#pragma unroll
            for (int j = 0; j < 4; j += 2) {
                const int c = col0 + tx * 4 + j;   // even column
                const int d = c & 63;              // even d
                const float cs = freqs[(size_t)r * HD + d];
                const float sn = freqs[(size_t)TT * HD + (size_t)r * HD + d];
                const float v0 = acc[i][j], v1 = acc[i][j + 1];
                const float o0 = v0 * cs - v1 * sn;
                const float o1 = v1 * cs + v0 * sn;
                if (MODE == 1) {
                    g_Q[(size_t)r * DM + c]     = o0;
                    g_Q[(size_t)r * DM + c + 1] = o1;
                } else {  // MODE 2
                    const int kv = c >> 6;
                    const size_t base = ((size_t)kv * TT + r) * HD + d;
                    g_K[base]     = o0;
                    g_K[base + 1] = o1;
                }
            }
        }
    }
}

// ---------------------------------------------------------------------------
// Flash attention (causal, GQA). Grid: (32 heads, 16 query tiles), 128 threads.
// One query per thread; q[64], acc[64], s[32] in registers.
// K/V tiles of 32 keys staged in smem (broadcast reads in inner loops).
// ---------------------------------------------------------------------------
__global__ __launch_bounds__(128)
void attn_kernel()
{
    __shared__ __align__(16) float Ks[32][64];
    __shared__ __align__(16) float Vs[32][64];

    const int h  = blockIdx.x;          // 0..31
    const int qt = blockIdx.y;          // 0..15
    const int kv = h >> 2;
    const int tid = threadIdx.x;
    const int tq = qt * 128 + tid;      // this thread's query token

    const float scale = 0.125f;         // 1/sqrt(64)

    float q[64];
    {
        const float4* qp = (const float4*)(g_Q + (size_t)tq * DM + h * HD);
#pragma unroll
        for (int i = 0; i < 16; i++) {
            float4 v = qp[i];
            q[4 * i + 0] = v.x * scale;
            q[4 * i + 1] = v.y * scale;
            q[4 * i + 2] = v.z * scale;
            q[4 * i + 3] = v.w * scale;
        }
    }

    float acc[64];
#pragma unroll
    for (int d = 0; d < 64; d++) acc[d] = 0.f;
    float m = -1e30f, l = 0.f;

    const float* kbase = g_K + (size_t)kv * TT * HD;
    const float* vbase = g_V + (size_t)kv * TT * HD;

    const int lrow = tid >> 2;          // 0..31
    const int lseg = (tid & 3) * 16;    // 0,16,32,48

    const int ntiles = qt * 4 + 4;      // keys [0, qt*128+128) in tiles of 32

    for (int kt = 0; kt < ntiles; kt++) {
        // cooperative load of 32x64 K and V tiles
        {
            const float4* ksrc = (const float4*)(kbase + ((size_t)(kt * 32 + lrow)) * HD + lseg);
            const float4* vsrc = (const float4*)(vbase + ((size_t)(kt * 32 + lrow)) * HD + lseg);
            float4* kdst = (float4*)&Ks[lrow][lseg];
            float4* vdst = (float4*)&Vs[lrow][lseg];
#pragma unroll
            for (int u = 0; u < 4; u++) kdst[u] = ksrc[u];
#pragma unroll
            for (int u = 0; u < 4; u++) vdst[u] = vsrc[u];
        }
        __syncthreads();

        // scores
        float s[32];
        float tmax = -1e30f;
#pragma unroll
        for (int j = 0; j < 32; j++) {
            float dot = 0.f;
            const float4* kr = (const float4*)Ks[j];
#pragma unroll
            for (int d4 = 0; d4 < 16; d4++) {
                float4 kx = kr[d4];
                dot = fmaf(q[4 * d4 + 0], kx.x, dot);
                dot = fmaf(q[4 * d4 + 1], kx.y, dot);
                dot = fmaf(q[4 * d4 + 2], kx.z, dot);
                dot = fmaf(q[4 * d4 + 3], kx.w, dot);
            }
            const int kj = kt * 32 + j;
            s[j] = (kj <= tq) ? dot : -1e30f;
            tmax = fmaxf(tmax, s[j]);
        }

        // online softmax update
        const float mnew = fmaxf(m, tmax);
        const float corr = __expf(m - mnew);
        m = mnew;
        l *= corr;
#pragma unroll
        for (int d = 0; d < 64; d++) acc[d] *= corr;

#pragma unroll
        for (int j = 0; j < 32; j++) {
            const float p = __expf(s[j] - m);
            l += p;
            const float4* vr = (const float4*)Vs[j];
#pragma unroll
            for (int d4 = 0; d4 < 16; d4++) {
                float4 vx = vr[d4];
                acc[4 * d4 + 0] = fmaf(p, vx.x, acc[4 * d4 + 0]);
                acc[4 * d4 + 1] = fmaf(p, vx.y, acc[4 * d4 + 1]);
                acc[4 * d4 + 2] = fmaf(p, vx.z, acc[4 * d4 + 2]);
                acc[4 * d4 + 3] = fmaf(p, vx.w, acc[4 * d4 + 3]);
            }
        }
        __syncthreads();
    }

    const float inv = 1.f / l;
    float* op = g_O + (size_t)tq * DM + h * HD;
#pragma unroll
    for (int d = 0; d < 64; d++) op[d] = acc[d] * inv;
}

// ---------------------------------------------------------------------------
// Launch
// ---------------------------------------------------------------------------
extern "C" void kernel_launch(void* const* d_in, const int* in_sizes, int n_in,
                              void* d_out, int out_size)
{
    const float* x     = (const float*)d_in[0];  // (1, 2048, 2048)
    const float* freqs = (const float*)d_in[1];  // (2, 2048, 64)
    // d_in[2] = mask (causal tril, implemented directly)
    const float* Wq    = (const float*)d_in[3];  // (2048, 2048)
    const float* Wk    = (const float*)d_in[4];  // (2048, 512)
    const float* Wv    = (const float*)d_in[5];  // (2048, 512)
    const float* Wo    = (const float*)d_in[6];  // (2048, 2048)
    float* out = (float*)d_out;

    dim3 blk(256);
    // Q projection + RoPE -> g_Q
    gemm_kernel<1><<<dim3(DM / 64, TT / 64), blk>>>(x, Wq, nullptr, DM, freqs);
    // K projection + RoPE -> g_K
    gemm_kernel<2><<<dim3((NKV * HD) / 64, TT / 64), blk>>>(x, Wk, nullptr, NKV * HD, freqs);
    // V projection -> g_V
    gemm_kernel<3><<<dim3((NKV * HD) / 64, TT / 64), blk>>>(x, Wv, nullptr, NKV * HD, nullptr);
    // attention -> g_O
    attn_kernel<<<dim3(NH, TT / 128), dim3(128)>>>();
    // output projection -> d_out
    gemm_kernel<0><<<dim3(DM / 64, TT / 64), blk>>>(nullptr, Wo, out, DM, nullptr);
}

// round 2
// speedup vs baseline: 1.8590x; 1.8590x over previous
#include <cuda_runtime.h>
#include <math.h>
#include <stdint.h>

#define TT   2048
#define DM   2048
#define NH   32
#define NKV  8
#define HD   64

__device__ float g_Q[TT * DM];
__device__ float g_K[NKV * TT * HD];
__device__ float g_V[NKV * TT * HD];
__device__ float g_O[TT * DM];

__device__ __forceinline__ float f2tf32(float x) {
    float y;
    asm("cvt.rna.tf32.f32 %0, %1;" : "=f"(y) : "f"(x));
    return y;
}

__device__ __forceinline__ void mma_tf32(float* d, const uint32_t* a, const uint32_t* b) {
    asm volatile(
        "mma.sync.aligned.m16n8k8.row.col.f32.tf32.tf32.f32 "
        "{%0,%1,%2,%3}, {%4,%5,%6,%7}, {%8,%9}, {%0,%1,%2,%3};"
        : "+f"(d[0]), "+f"(d[1]), "+f"(d[2]), "+f"(d[3])
        : "r"(a[0]), "r"(a[1]), "r"(a[2]), "r"(a[3]), "r"(b[0]), "r"(b[1]));
}

// ---------------------------------------------------------------------------
// TF32 tensor-core GEMM: C[M,N] = A[M,2048] @ B[2048,N]
// 128x128 CTA tile, BK=32, 256 threads (8 warps, 64x32 warp tile),
// mma.sync.m16n8k8.tf32. cvt.rna at smem store time.
// MODE 0: plain -> C (out proj, A = g_O)
// MODE 1: RoPE -> g_Q    MODE 2: RoPE -> g_K    MODE 3: plain -> g_V
// ---------------------------------------------------------------------------
template <int MODE>
__global__ __launch_bounds__(256)
void gemm_tc(const float* __restrict__ A, const float* __restrict__ B,
             float* __restrict__ C, int N, const float* __restrict__ freqs)
{
    __shared__ __align__(16) float As[128][36];   // [m][k], pad 36
    __shared__ __align__(16) float Bs[32][132];   // [k][n], pad 132

    const int tid  = threadIdx.x;
    const int lane = tid & 31;
    const int warp = tid >> 5;
    const int wm0  = (warp & 1) * 64;    // warp m offset in tile
    const int wn0  = (warp >> 1) * 32;   // warp n offset in tile
    const int row0 = blockIdx.y * 128;
    const int col0 = blockIdx.x * 128;

    const float* Ab = (MODE == 0) ? (const float*)g_O : A;

    // gmem load mapping
    const int ar = tid >> 3;            // 0..31 (4 rows: +32*i)
    const int ac = (tid & 7) * 4;       // k-offset within 32
    const int br = tid >> 6;            // 0..3  (+4*i? no: rows tid>>5 below)
    (void)br;
    const int bkr = tid >> 5;           // 0..7  (4 rows: +8*i)
    const int bc  = (lane) * 4;         // n-offset 0..124

    float4 aReg[4], bReg[4];

    const float* Aptr = Ab + (size_t)(row0 + ar) * DM + ac;
    const float* Bptr = B + (size_t)bkr * N + col0 + bc;

    // prefetch k0 = 0
#pragma unroll
    for (int i = 0; i < 4; i++) aReg[i] = *(const float4*)(Aptr + (size_t)(32 * i) * DM);
#pragma unroll
    for (int i = 0; i < 4; i++) bReg[i] = *(const float4*)(Bptr + (size_t)(8 * i) * N);

    float acc[4][4][4];
#pragma unroll
    for (int mt = 0; mt < 4; mt++)
#pragma unroll
        for (int nt = 0; nt < 4; nt++)
#pragma unroll
            for (int u = 0; u < 4; u++) acc[mt][nt][u] = 0.f;

    const int grp = lane >> 2;          // 0..7
    const int tig = lane & 3;           // 0..3

    for (int k0 = 0; k0 < DM; k0 += 32) {
        // stage regs -> smem (convert to tf32)
#pragma unroll
        for (int i = 0; i < 4; i++) {
            As[ar + 32 * i][ac + 0] = f2tf32(aReg[i].x);
            As[ar + 32 * i][ac + 1] = f2tf32(aReg[i].y);
            As[ar + 32 * i][ac + 2] = f2tf32(aReg[i].z);
            As[ar + 32 * i][ac + 3] = f2tf32(aReg[i].w);
        }
#pragma unroll
        for (int i = 0; i < 4; i++) {
            Bs[bkr + 8 * i][bc + 0] = f2tf32(bReg[i].x);
            Bs[bkr + 8 * i][bc + 1] = f2tf32(bReg[i].y);
            Bs[bkr + 8 * i][bc + 2] = f2tf32(bReg[i].z);
            Bs[bkr + 8 * i][bc + 3] = f2tf32(bReg[i].w);
        }
        __syncthreads();

        // prefetch next k-slab while computing
        if (k0 + 32 < DM) {
#pragma unroll
            for (int i = 0; i < 4; i++)
                aReg[i] = *(const float4*)(Aptr + (size_t)(k0 + 32) + (size_t)(32 * i) * DM);
#pragma unroll
            for (int i = 0; i < 4; i++)
                bReg[i] = *(const float4*)(Bptr + (size_t)(k0 + 32 + 8 * i) * N);
        }

#pragma unroll
        for (int ks = 0; ks < 4; ks++) {
            const int kc = ks * 8 + tig;
            uint32_t afr[4][4], bfr[4][2];
#pragma unroll
            for (int mt = 0; mt < 4; mt++) {
                const int r = wm0 + mt * 16 + grp;
                afr[mt][0] = __float_as_uint(As[r][kc]);
                afr[mt][1] = __float_as_uint(As[r + 8][kc]);
                afr[mt][2] = __float_as_uint(As[r][kc + 4]);
                afr[mt][3] = __float_as_uint(As[r + 8][kc + 4]);
            }
#pragma unroll
            for (int nt = 0; nt < 4; nt++) {
                const int c = wn0 + nt * 8 + grp;
                bfr[nt][0] = __float_as_uint(Bs[ks * 8 + tig][c]);
                bfr[nt][1] = __float_as_uint(Bs[ks * 8 + tig + 4][c]);
            }
#pragma unroll
            for (int mt = 0; mt < 4; mt++)
#pragma unroll
                for (int nt = 0; nt < 4; nt++)
                    mma_tf32(acc[mt][nt], afr[mt], bfr[nt]);
        }
        __syncthreads();
    }

    // Epilogue. C fragment: c0 (r=grp, c=tig*2), c1 (c+1), c2 (r+8), c3 (r+8,c+1)
#pragma unroll
    for (int mt = 0; mt < 4; mt++) {
#pragma unroll
        for (int nt = 0; nt < 4; nt++) {
            const int rb = row0 + wm0 + mt * 16 + grp;
            const int cb = col0 + wn0 + nt * 8 + tig * 2;   // even column
#pragma unroll
            for (int half = 0; half < 2; half++) {
                const int r = rb + half * 8;
                const float v0 = acc[mt][nt][half * 2 + 0];
                const float v1 = acc[mt][nt][half * 2 + 1];
                if (MODE == 0) {
                    C[(size_t)r * N + cb]     = v0;
                    C[(size_t)r * N + cb + 1] = v1;
                } else if (MODE == 3) {
                    const int kv = cb >> 6, d = cb & 63;
                    const size_t base = ((size_t)kv * TT + r) * HD + d;
                    g_V[base]     = v0;
                    g_V[base + 1] = v1;
                } else {
                    const int d = cb & 63;   // even
                    const float cs = freqs[(size_t)r * HD + d];
                    const float sn = freqs[(size_t)TT * HD + (size_t)r * HD + d];
                    const float o0 = v0 * cs - v1 * sn;
                    const float o1 = v1 * cs + v0 * sn;
                    if (MODE == 1) {
                        g_Q[(size_t)r * DM + cb]     = o0;
                        g_Q[(size_t)r * DM + cb + 1] = o1;
                    } else {
                        const int kv = cb >> 6;
                        const size_t base = ((size_t)kv * TT + r) * HD + d;
                        g_K[base]     = o0;
                        g_K[base + 1] = o1;
                    }
                }
            }
        }
    }
}

// ---------------------------------------------------------------------------
// Flash attention, split-D: 2 threads per query (32 dims each), 256 threads,
// 128 queries/CTA. K/V tiles 32x64 in smem with +4 half-offset to avoid
// bank conflicts between the two D-halves.
// ---------------------------------------------------------------------------
__global__ __launch_bounds__(256, 2)
void attn_kernel()
{
    __shared__ __align__(16) float Ks[32][72];
    __shared__ __align__(16) float Vs[32][72];

    const int h  = blockIdx.x;
    const int qt = blockIdx.y;
    const int kv = h >> 2;
    const int tid = threadIdx.x;
    const int half = tid & 1;
    const int tq = qt * 128 + (tid >> 1);
    const int off = half * 36;           // smem col offset of this half
    const int dof = half * 32;           // dim offset

    const float scale = 0.125f;

    float q[32];
    {
        const float4* qp = (const float4*)(g_Q + (size_t)tq * DM + h * HD + dof);
#pragma unroll
        for (int i = 0; i < 8; i++) {
            float4 v = qp[i];
            q[4 * i + 0] = v.x * scale;
            q[4 * i + 1] = v.y * scale;
            q[4 * i + 2] = v.z * scale;
            q[4 * i + 3] = v.w * scale;
        }
    }

    float acc[32];
#pragma unroll
    for (int d = 0; d < 32; d++) acc[d] = 0.f;
    float m = -1e30f, l = 0.f;

    const float* kbase = g_K + (size_t)kv * TT * HD;
    const float* vbase = g_V + (size_t)kv * TT * HD;

    const int lrow = tid >> 3;                         // 0..31
    const int lcol = (tid & 7) * 8;                    // 0..56
    const int pcol = lcol + (lcol >= 32 ? 4 : 0);      // physical col

    const int ntiles = (qt + 1) * 4;

    for (int kt = 0; kt < ntiles; kt++) {
        {
            const float* ksrc = kbase + ((size_t)(kt * 32 + lrow)) * HD + lcol;
            const float* vsrc = vbase + ((size_t)(kt * 32 + lrow)) * HD + lcol;
            *(float4*)&Ks[lrow][pcol]     = *(const float4*)(ksrc);
            *(float4*)&Ks[lrow][pcol + 4] = *(const float4*)(ksrc + 4);
            *(float4*)&Vs[lrow][pcol]     = *(const float4*)(vsrc);
            *(float4*)&Vs[lrow][pcol + 4] = *(const float4*)(vsrc + 4);
        }
        __syncthreads();

        float s[32];
        float tmax = -1e30f;
#pragma unroll
        for (int j = 0; j < 32; j++) {
            float dot = 0.f;
            const float4* kr = (const float4*)&Ks[j][off];
#pragma unroll
            for (int d4 = 0; d4 < 8; d4++) {
                float4 kx = kr[d4];
                dot = fmaf(q[4 * d4 + 0], kx.x, dot);
                dot = fmaf(q[4 * d4 + 1], kx.y, dot);
                dot = fmaf(q[4 * d4 + 2], kx.z, dot);
                dot = fmaf(q[4 * d4 + 3], kx.w, dot);
            }
            dot += __shfl_xor_sync(0xffffffffu, dot, 1);
            const int kj = kt * 32 + j;
            s[j] = (kj <= tq) ? dot : -1e30f;
            tmax = fmaxf(tmax, s[j]);
        }

        const float mnew = fmaxf(m, tmax);
        const float corr = __expf(m - mnew);
        m = mnew;
        l *= corr;
#pragma unroll
        for (int d = 0; d < 32; d++) acc[d] *= corr;

#pragma unroll
        for (int j = 0; j < 32; j++) {
            const float p = __expf(s[j] - m);
            l += p;
            const float4* vr = (const float4*)&Vs[j][off];
#pragma unroll
            for (int d4 = 0; d4 < 8; d4++) {
                float4 vx = vr[d4];
                acc[4 * d4 + 0] = fmaf(p, vx.x, acc[4 * d4 + 0]);
                acc[4 * d4 + 1] = fmaf(p, vx.y, acc[4 * d4 + 1]);
                acc[4 * d4 + 2] = fmaf(p, vx.z, acc[4 * d4 + 2]);
                acc[4 * d4 + 3] = fmaf(p, vx.w, acc[4 * d4 + 3]);
            }
        }
        __syncthreads();
    }

    const float inv = 1.f / l;
    float* op = g_O + (size_t)tq * DM + h * HD + dof;
#pragma unroll
    for (int d = 0; d < 32; d++) op[d] = acc[d] * inv;
}

// ---------------------------------------------------------------------------
extern "C" void kernel_launch(void* const* d_in, const int* in_sizes, int n_in,
                              void* d_out, int out_size)
{
    const float* x     = (const float*)d_in[0];
    const float* freqs = (const float*)d_in[1];
    const float* Wq    = (const float*)d_in[3];
    const float* Wk    = (const float*)d_in[4];
    const float* Wv    = (const float*)d_in[5];
    const float* Wo    = (const float*)d_in[6];
    float* out = (float*)d_out;

    dim3 blk(256);
    gemm_tc<1><<<dim3(DM / 128, TT / 128), blk>>>(x, Wq, nullptr, DM, freqs);
    gemm_tc<2><<<dim3((NKV * HD) / 128, TT / 128), blk>>>(x, Wk, nullptr, NKV * HD, freqs);
    gemm_tc<3><<<dim3((NKV * HD) / 128, TT / 128), blk>>>(x, Wv, nullptr, NKV * HD, nullptr);
    attn_kernel<<<dim3(NH, TT / 128), dim3(256)>>>();
    gemm_tc<0><<<dim3(DM / 128, TT / 128), blk>>>(nullptr, Wo, out, DM, nullptr);
}

// round 3
// speedup vs baseline: 3.5124x; 1.8894x over previous
#include <cuda_runtime.h>
#include <math.h>
#include <stdint.h>

#define TT   2048
#define DM   2048
#define NH   32
#define NKV  8
#define HD   64

__device__ float g_Q[TT * DM];
__device__ float g_K[NKV * TT * HD];
__device__ float g_V[NKV * TT * HD];
__device__ float g_O[TT * DM];

__device__ __forceinline__ float f2tf32(float x) {
    float y;
    asm("cvt.rna.tf32.f32 %0, %1;" : "=f"(y) : "f"(x));
    return y;
}

__device__ __forceinline__ void mma_tf32(float* d, const uint32_t* a, const uint32_t* b) {
    asm volatile(
        "mma.sync.aligned.m16n8k8.row.col.f32.tf32.tf32.f32 "
        "{%0,%1,%2,%3}, {%4,%5,%6,%7}, {%8,%9}, {%0,%1,%2,%3};"
        : "+f"(d[0]), "+f"(d[1]), "+f"(d[2]), "+f"(d[3])
        : "r"(a[0]), "r"(a[1]), "r"(a[2]), "r"(a[3]), "r"(b[0]), "r"(b[1]));
}

// ---------------------------------------------------------------------------
// TF32 tensor-core GEMM (unchanged from R2): C[M,N] = A[M,2048] @ B[2048,N]
// ---------------------------------------------------------------------------
template <int MODE>
__global__ __launch_bounds__(256)
void gemm_tc(const float* __restrict__ A, const float* __restrict__ B,
             float* __restrict__ C, int N, const float* __restrict__ freqs)
{
    __shared__ __align__(16) float As[128][36];
    __shared__ __align__(16) float Bs[32][132];

    const int tid  = threadIdx.x;
    const int lane = tid & 31;
    const int warp = tid >> 5;
    const int wm0  = (warp & 1) * 64;
    const int wn0  = (warp >> 1) * 32;
    const int row0 = blockIdx.y * 128;
    const int col0 = blockIdx.x * 128;

    const float* Ab = (MODE == 0) ? (const float*)g_O : A;

    const int ar = tid >> 3;
    const int ac = (tid & 7) * 4;
    const int bkr = tid >> 5;
    const int bc  = lane * 4;

    float4 aReg[4], bReg[4];
    const float* Aptr = Ab + (size_t)(row0 + ar) * DM + ac;
    const float* Bptr = B + (size_t)bkr * N + col0 + bc;

#pragma unroll
    for (int i = 0; i < 4; i++) aReg[i] = *(const float4*)(Aptr + (size_t)(32 * i) * DM);
#pragma unroll
    for (int i = 0; i < 4; i++) bReg[i] = *(const float4*)(Bptr + (size_t)(8 * i) * N);

    float acc[4][4][4];
#pragma unroll
    for (int mt = 0; mt < 4; mt++)
#pragma unroll
        for (int nt = 0; nt < 4; nt++)
#pragma unroll
            for (int u = 0; u < 4; u++) acc[mt][nt][u] = 0.f;

    const int grp = lane >> 2;
    const int tig = lane & 3;

    for (int k0 = 0; k0 < DM; k0 += 32) {
#pragma unroll
        for (int i = 0; i < 4; i++) {
            As[ar + 32 * i][ac + 0] = f2tf32(aReg[i].x);
            As[ar + 32 * i][ac + 1] = f2tf32(aReg[i].y);
            As[ar + 32 * i][ac + 2] = f2tf32(aReg[i].z);
            As[ar + 32 * i][ac + 3] = f2tf32(aReg[i].w);
        }
#pragma unroll
        for (int i = 0; i < 4; i++) {
            Bs[bkr + 8 * i][bc + 0] = f2tf32(bReg[i].x);
            Bs[bkr + 8 * i][bc + 1] = f2tf32(bReg[i].y);
            Bs[bkr + 8 * i][bc + 2] = f2tf32(bReg[i].z);
            Bs[bkr + 8 * i][bc + 3] = f2tf32(bReg[i].w);
        }
        __syncthreads();

        if (k0 + 32 < DM) {
#pragma unroll
            for (int i = 0; i < 4; i++)
                aReg[i] = *(const float4*)(Aptr + (size_t)(k0 + 32) + (size_t)(32 * i) * DM);
#pragma unroll
            for (int i = 0; i < 4; i++)
                bReg[i] = *(const float4*)(Bptr + (size_t)(k0 + 32 + 8 * i) * N);
        }

#pragma unroll
        for (int ks = 0; ks < 4; ks++) {
            const int kc = ks * 8 + tig;
            uint32_t afr[4][4], bfr[4][2];
#pragma unroll
            for (int mt = 0; mt < 4; mt++) {
                const int r = wm0 + mt * 16 + grp;
                afr[mt][0] = __float_as_uint(As[r][kc]);
                afr[mt][1] = __float_as_uint(As[r + 8][kc]);
                afr[mt][2] = __float_as_uint(As[r][kc + 4]);
                afr[mt][3] = __float_as_uint(As[r + 8][kc + 4]);
            }
#pragma unroll
            for (int nt = 0; nt < 4; nt++) {
                const int c = wn0 + nt * 8 + grp;
                bfr[nt][0] = __float_as_uint(Bs[ks * 8 + tig][c]);
                bfr[nt][1] = __float_as_uint(Bs[ks * 8 + tig + 4][c]);
            }
#pragma unroll
            for (int mt = 0; mt < 4; mt++)
#pragma unroll
                for (int nt = 0; nt < 4; nt++)
                    mma_tf32(acc[mt][nt], afr[mt], bfr[nt]);
        }
        __syncthreads();
    }

#pragma unroll
    for (int mt = 0; mt < 4; mt++) {
#pragma unroll
        for (int nt = 0; nt < 4; nt++) {
            const int rb = row0 + wm0 + mt * 16 + grp;
            const int cb = col0 + wn0 + nt * 8 + tig * 2;
#pragma unroll
            for (int half = 0; half < 2; half++) {
                const int r = rb + half * 8;
                const float v0 = acc[mt][nt][half * 2 + 0];
                const float v1 = acc[mt][nt][half * 2 + 1];
                if (MODE == 0) {
                    C[(size_t)r * N + cb]     = v0;
                    C[(size_t)r * N + cb + 1] = v1;
                } else if (MODE == 3) {
                    const int kv = cb >> 6, d = cb & 63;
                    const size_t base = ((size_t)kv * TT + r) * HD + d;
                    g_V[base]     = v0;
                    g_V[base + 1] = v1;
                } else {
                    const int d = cb & 63;
                    const float cs = freqs[(size_t)r * HD + d];
                    const float sn = freqs[(size_t)TT * HD + (size_t)r * HD + d];
                    const float o0 = v0 * cs - v1 * sn;
                    const float o1 = v1 * cs + v0 * sn;
                    if (MODE == 1) {
                        g_Q[(size_t)r * DM + cb]     = o0;
                        g_Q[(size_t)r * DM + cb + 1] = o1;
                    } else {
                        const int kv = cb >> 6;
                        const size_t base = ((size_t)kv * TT + r) * HD + d;
                        g_K[base]     = o0;
                        g_K[base + 1] = o1;
                    }
                }
            }
        }
    }
}

// ---------------------------------------------------------------------------
// Tensor-core flash attention (causal, GQA).
// CTA: 1 head x 64 queries. 4 warps, 16 query rows each. Key tiles of 64.
// S = Q K^T and O += P V both via mma.m16n8k8.tf32.
// ---------------------------------------------------------------------------
__global__ __launch_bounds__(128, 3)
void attn_tc_kernel()
{
    __shared__ __align__(16) float Ks[64][68];
    __shared__ __align__(16) float Vs[64][68];

    const int h   = blockIdx.x;
    const int qb  = (TT / 64 - 1) - blockIdx.y;   // heavy blocks first
    const int kvh = h >> 2;
    const int tid  = threadIdx.x;
    const int lane = tid & 31;
    const int warp = tid >> 5;
    const int wm0  = warp * 16;
    const int grp  = lane >> 2;
    const int tig  = lane & 3;

    const float* kbase = g_K + (size_t)kvh * TT * HD;
    const float* vbase = g_V + (size_t)kvh * TT * HD;

    // ---- stage Q (scaled, tf32) through Ks, build A-fragments ----
    {
        const float* qsrc = g_Q + ((size_t)(qb * 64)) * DM + h * HD;
#pragma unroll
        for (int i = 0; i < 8; i++) {
            const int j = i * 128 + tid;
            const int row = j >> 4, c4 = (j & 15) * 4;
            float4 v = *(const float4*)(qsrc + (size_t)row * DM + c4);
            Ks[row][c4 + 0] = f2tf32(v.x * 0.125f);
            Ks[row][c4 + 1] = f2tf32(v.y * 0.125f);
            Ks[row][c4 + 2] = f2tf32(v.z * 0.125f);
            Ks[row][c4 + 3] = f2tf32(v.w * 0.125f);
        }
    }
    __syncthreads();

    uint32_t qf[8][4];
#pragma unroll
    for (int ks = 0; ks < 8; ks++) {
        qf[ks][0] = __float_as_uint(Ks[wm0 + grp][8 * ks + tig]);
        qf[ks][1] = __float_as_uint(Ks[wm0 + grp + 8][8 * ks + tig]);
        qf[ks][2] = __float_as_uint(Ks[wm0 + grp][8 * ks + tig + 4]);
        qf[ks][3] = __float_as_uint(Ks[wm0 + grp + 8][8 * ks + tig + 4]);
    }
    __syncthreads();

    float acc[8][4];
#pragma unroll
    for (int nt = 0; nt < 8; nt++)
#pragma unroll
        for (int u = 0; u < 4; u++) acc[nt][u] = 0.f;
    float m0 = -1e30f, m1 = -1e30f, l0 = 0.f, l1 = 0.f;

    const int src0 = (lane & ~3) + (tig >> 1);
    const int src1 = src0 + 2;
    const bool odd = tig & 1;

    for (int kt = 0; kt <= qb; kt++) {
        // ---- load K,V 64x64 tiles (tf32) ----
#pragma unroll
        for (int i = 0; i < 8; i++) {
            const int j = i * 128 + tid;
            const int row = j >> 4, c4 = (j & 15) * 4;
            const size_t goff = ((size_t)(kt * 64 + row)) * HD + c4;
            float4 kx = *(const float4*)(kbase + goff);
            float4 vx = *(const float4*)(vbase + goff);
            Ks[row][c4 + 0] = f2tf32(kx.x);
            Ks[row][c4 + 1] = f2tf32(kx.y);
            Ks[row][c4 + 2] = f2tf32(kx.z);
            Ks[row][c4 + 3] = f2tf32(kx.w);
            Vs[row][c4 + 0] = f2tf32(vx.x);
            Vs[row][c4 + 1] = f2tf32(vx.y);
            Vs[row][c4 + 2] = f2tf32(vx.z);
            Vs[row][c4 + 3] = f2tf32(vx.w);
        }
        __syncthreads();

        // ---- S = Q K^T ----
        float s[8][4];
#pragma unroll
        for (int nt = 0; nt < 8; nt++)
#pragma unroll
            for (int u = 0; u < 4; u++) s[nt][u] = 0.f;

#pragma unroll
        for (int ks = 0; ks < 8; ks++) {
#pragma unroll
            for (int nt = 0; nt < 8; nt++) {
                uint32_t b[2];
                b[0] = __float_as_uint(Ks[8 * nt + grp][8 * ks + tig]);
                b[1] = __float_as_uint(Ks[8 * nt + grp][8 * ks + tig + 4]);
                mma_tf32(s[nt], qf[ks], b);
            }
        }

        // ---- causal mask on diagonal tile ----
        if (kt == qb) {
            const int r0 = wm0 + grp, r1 = r0 + 8;
#pragma unroll
            for (int nt = 0; nt < 8; nt++) {
                const int c = 8 * nt + 2 * tig;
                if (c > r0)     s[nt][0] = -1e30f;
                if (c + 1 > r0) s[nt][1] = -1e30f;
                if (c > r1)     s[nt][2] = -1e30f;
                if (c + 1 > r1) s[nt][3] = -1e30f;
            }
        }

        // ---- online softmax ----
        float t0 = -1e30f, t1 = -1e30f;
#pragma unroll
        for (int nt = 0; nt < 8; nt++) {
            t0 = fmaxf(t0, fmaxf(s[nt][0], s[nt][1]));
            t1 = fmaxf(t1, fmaxf(s[nt][2], s[nt][3]));
        }
        t0 = fmaxf(t0, __shfl_xor_sync(0xffffffffu, t0, 1));
        t0 = fmaxf(t0, __shfl_xor_sync(0xffffffffu, t0, 2));
        t1 = fmaxf(t1, __shfl_xor_sync(0xffffffffu, t1, 1));
        t1 = fmaxf(t1, __shfl_xor_sync(0xffffffffu, t1, 2));

        const float mn0 = fmaxf(m0, t0), mn1 = fmaxf(m1, t1);
        const float cr0 = __expf(m0 - mn0), cr1 = __expf(m1 - mn1);
        m0 = mn0; m1 = mn1;
        l0 *= cr0; l1 *= cr1;
#pragma unroll
        for (int nt = 0; nt < 8; nt++) {
            acc[nt][0] *= cr0; acc[nt][1] *= cr0;
            acc[nt][2] *= cr1; acc[nt][3] *= cr1;
        }

#pragma unroll
        for (int nt = 0; nt < 8; nt++) {
            float p0 = f2tf32(__expf(s[nt][0] - m0));
            float p1 = f2tf32(__expf(s[nt][1] - m0));
            float p2 = f2tf32(__expf(s[nt][2] - m1));
            float p3 = f2tf32(__expf(s[nt][3] - m1));
            l0 += p0 + p1; l1 += p2 + p3;
            s[nt][0] = p0; s[nt][1] = p1; s[nt][2] = p2; s[nt][3] = p3;
        }

        // ---- O += P V ----
#pragma unroll
        for (int ks = 0; ks < 8; ks++) {
            uint32_t a[4];
            {
                float v0 = __shfl_sync(0xffffffffu, s[ks][0], src0);
                float v1 = __shfl_sync(0xffffffffu, s[ks][1], src0);
                float v2 = __shfl_sync(0xffffffffu, s[ks][2], src0);
                float v3 = __shfl_sync(0xffffffffu, s[ks][3], src0);
                float w0 = __shfl_sync(0xffffffffu, s[ks][0], src1);
                float w1 = __shfl_sync(0xffffffffu, s[ks][1], src1);
                float w2 = __shfl_sync(0xffffffffu, s[ks][2], src1);
                float w3 = __shfl_sync(0xffffffffu, s[ks][3], src1);
                a[0] = __float_as_uint(odd ? v1 : v0);
                a[1] = __float_as_uint(odd ? v3 : v2);
                a[2] = __float_as_uint(odd ? w1 : w0);
                a[3] = __float_as_uint(odd ? w3 : w2);
            }
#pragma unroll
            for (int nt = 0; nt < 8; nt++) {
                uint32_t b[2];
                b[0] = __float_as_uint(Vs[8 * ks + tig][8 * nt + grp]);
                b[1] = __float_as_uint(Vs[8 * ks + tig + 4][8 * nt + grp]);
                mma_tf32(acc[nt], a, b);
            }
        }
        __syncthreads();
    }

    // ---- epilogue ----
    l0 += __shfl_xor_sync(0xffffffffu, l0, 1);
    l0 += __shfl_xor_sync(0xffffffffu, l0, 2);
    l1 += __shfl_xor_sync(0xffffffffu, l1, 1);
    l1 += __shfl_xor_sync(0xffffffffu, l1, 2);
    const float i0 = 1.f / l0, i1 = 1.f / l1;

    const int tq0 = qb * 64 + wm0 + grp;
    float* o0 = g_O + (size_t)tq0 * DM + h * HD;
    float* o1 = o0 + (size_t)8 * DM;
#pragma unroll
    for (int nt = 0; nt < 8; nt++) {
        const int c = 8 * nt + 2 * tig;
        float2 u0 = make_float2(acc[nt][0] * i0, acc[nt][1] * i0);
        float2 u1 = make_float2(acc[nt][2] * i1, acc[nt][3] * i1);
        *(float2*)(o0 + c) = u0;
        *(float2*)(o1 + c) = u1;
    }
}

// ---------------------------------------------------------------------------
extern "C" void kernel_launch(void* const* d_in, const int* in_sizes, int n_in,
                              void* d_out, int out_size)
{
    const float* x     = (const float*)d_in[0];
    const float* freqs = (const float*)d_in[1];
    const float* Wq    = (const float*)d_in[3];
    const float* Wk    = (const float*)d_in[4];
    const float* Wv    = (const float*)d_in[5];
    const float* Wo    = (const float*)d_in[6];
    float* out = (float*)d_out;

    dim3 blk(256);
    gemm_tc<1><<<dim3(DM / 128, TT / 128), blk>>>(x, Wq, nullptr, DM, freqs);
    gemm_tc<2><<<dim3((NKV * HD) / 128, TT / 128), blk>>>(x, Wk, nullptr, NKV * HD, freqs);
    gemm_tc<3><<<dim3((NKV * HD) / 128, TT / 128), blk>>>(x, Wv, nullptr, NKV * HD, nullptr);
    attn_tc_kernel<<<dim3(NH, TT / 64), dim3(128)>>>();
    gemm_tc<0><<<dim3(DM / 128, TT / 128), blk>>>(nullptr, Wo, out, DM, nullptr);
}

// round 4
// speedup vs baseline: 4.2011x; 1.1961x over previous
#include <cuda_runtime.h>
#include <math.h>
#include <stdint.h>

#define TT   2048
#define DM   2048
#define NH   32
#define NKV  8
#define HD   64

__device__ float g_Q[TT * DM];
__device__ float g_K[NKV * TT * HD];
__device__ float g_V[NKV * TT * HD];
__device__ float g_O[TT * DM];

__device__ __forceinline__ float f2tf32(float x) {
    float y;
    asm("cvt.rna.tf32.f32 %0, %1;" : "=f"(y) : "f"(x));
    return y;
}

__device__ __forceinline__ void mma_tf32(float* d, const uint32_t* a, const uint32_t* b) {
    asm volatile(
        "mma.sync.aligned.m16n8k8.row.col.f32.tf32.tf32.f32 "
        "{%0,%1,%2,%3}, {%4,%5,%6,%7}, {%8,%9}, {%0,%1,%2,%3};"
        : "+f"(d[0]), "+f"(d[1]), "+f"(d[2]), "+f"(d[3])
        : "r"(a[0]), "r"(a[1]), "r"(a[2]), "r"(a[3]), "r"(b[0]), "r"(b[1]));
}

// ---------------------------------------------------------------------------
// TF32 GEMM, 128x128x32 tiles, 256 thr, double-buffered smem (1 sync/slab).
// QKV=true : A = x, virtual N=3072 -> segments [Wq | Wk | Wv] with per-CTA
//            epilogue mode (RoPE->g_Q, RoPE->g_K, plain->g_V).
// QKV=false: A = g_O, B = Wo, plain store to Cout.
// ---------------------------------------------------------------------------
template <bool QKV>
__global__ __launch_bounds__(256)
void gemm_tc(const float* __restrict__ x, const float* __restrict__ Wq,
             const float* __restrict__ Wk, const float* __restrict__ Wv,
             const float* __restrict__ Wo, float* __restrict__ Cout,
             const float* __restrict__ freqs)
{
    __shared__ __align__(16) float As[2][128][36];
    __shared__ __align__(16) float Bs[2][32][132];

    const int tid  = threadIdx.x;
    const int lane = tid & 31;
    const int warp = tid >> 5;
    const int wm0  = (warp & 1) * 64;
    const int wn0  = (warp >> 1) * 32;
    const int row0 = blockIdx.y * 128;

    // segment select
    int mode, N, lcol0;
    const float* A;
    const float* B;
    if (QKV) {
        const int col0 = blockIdx.x * 128;
        A = x;
        if (col0 < 2048)      { B = Wq; N = 2048; lcol0 = col0;        mode = 1; }
        else if (col0 < 2560) { B = Wk; N = 512;  lcol0 = col0 - 2048; mode = 2; }
        else                  { B = Wv; N = 512;  lcol0 = col0 - 2560; mode = 3; }
    } else {
        A = (const float*)g_O; B = Wo; N = 2048; lcol0 = blockIdx.x * 128; mode = 0;
    }

    const int ar  = tid >> 3;
    const int ac  = (tid & 7) * 4;
    const int bkr = tid >> 5;
    const int bc  = lane * 4;

    const float* Aptr = A + (size_t)(row0 + ar) * DM + ac;
    const float* Bptr = B + (size_t)bkr * N + lcol0 + bc;

    float4 aReg[4], bReg[4];
#pragma unroll
    for (int i = 0; i < 4; i++) aReg[i] = *(const float4*)(Aptr + (size_t)(32 * i) * DM);
#pragma unroll
    for (int i = 0; i < 4; i++) bReg[i] = *(const float4*)(Bptr + (size_t)(8 * i) * N);

    float acc[4][4][4];
#pragma unroll
    for (int mt = 0; mt < 4; mt++)
#pragma unroll
        for (int nt = 0; nt < 4; nt++)
#pragma unroll
            for (int u = 0; u < 4; u++) acc[mt][nt][u] = 0.f;

    const int grp = lane >> 2;
    const int tig = lane & 3;

    // stage slab 0 into buf 0
#pragma unroll
    for (int i = 0; i < 4; i++) {
        As[0][ar + 32 * i][ac + 0] = f2tf32(aReg[i].x);
        As[0][ar + 32 * i][ac + 1] = f2tf32(aReg[i].y);
        As[0][ar + 32 * i][ac + 2] = f2tf32(aReg[i].z);
        As[0][ar + 32 * i][ac + 3] = f2tf32(aReg[i].w);
    }
#pragma unroll
    for (int i = 0; i < 4; i++) {
        Bs[0][bkr + 8 * i][bc + 0] = f2tf32(bReg[i].x);
        Bs[0][bkr + 8 * i][bc + 1] = f2tf32(bReg[i].y);
        Bs[0][bkr + 8 * i][bc + 2] = f2tf32(bReg[i].z);
        Bs[0][bkr + 8 * i][bc + 3] = f2tf32(bReg[i].w);
    }
    __syncthreads();

    for (int k0 = 0; k0 < DM; k0 += 32) {
        const int cur = (k0 >> 5) & 1;
        const int nxt = cur ^ 1;
        const bool more = (k0 + 32) < DM;

        if (more) {
#pragma unroll
            for (int i = 0; i < 4; i++)
                aReg[i] = *(const float4*)(Aptr + (size_t)(k0 + 32) + (size_t)(32 * i) * DM);
#pragma unroll
            for (int i = 0; i < 4; i++)
                bReg[i] = *(const float4*)(Bptr + (size_t)(k0 + 32 + 8 * i) * N);
        }

#pragma unroll
        for (int ks = 0; ks < 4; ks++) {
            const int kc = ks * 8 + tig;
            uint32_t afr[4][4], bfr[4][2];
#pragma unroll
            for (int mt = 0; mt < 4; mt++) {
                const int r = wm0 + mt * 16 + grp;
                afr[mt][0] = __float_as_uint(As[cur][r][kc]);
                afr[mt][1] = __float_as_uint(As[cur][r + 8][kc]);
                afr[mt][2] = __float_as_uint(As[cur][r][kc + 4]);
                afr[mt][3] = __float_as_uint(As[cur][r + 8][kc + 4]);
            }
#pragma unroll
            for (int nt = 0; nt < 4; nt++) {
                const int c = wn0 + nt * 8 + grp;
                bfr[nt][0] = __float_as_uint(Bs[cur][ks * 8 + tig][c]);
                bfr[nt][1] = __float_as_uint(Bs[cur][ks * 8 + tig + 4][c]);
            }
#pragma unroll
            for (int mt = 0; mt < 4; mt++)
#pragma unroll
                for (int nt = 0; nt < 4; nt++)
                    mma_tf32(acc[mt][nt], afr[mt], bfr[nt]);
        }

        if (more) {
#pragma unroll
            for (int i = 0; i < 4; i++) {
                As[nxt][ar + 32 * i][ac + 0] = f2tf32(aReg[i].x);
                As[nxt][ar + 32 * i][ac + 1] = f2tf32(aReg[i].y);
                As[nxt][ar + 32 * i][ac + 2] = f2tf32(aReg[i].z);
                As[nxt][ar + 32 * i][ac + 3] = f2tf32(aReg[i].w);
            }
#pragma unroll
            for (int i = 0; i < 4; i++) {
                Bs[nxt][bkr + 8 * i][bc + 0] = f2tf32(bReg[i].x);
                Bs[nxt][bkr + 8 * i][bc + 1] = f2tf32(bReg[i].y);
                Bs[nxt][bkr + 8 * i][bc + 2] = f2tf32(bReg[i].z);
                Bs[nxt][bkr + 8 * i][bc + 3] = f2tf32(bReg[i].w);
            }
        }
        __syncthreads();
    }

    // epilogue
#pragma unroll
    for (int mt = 0; mt < 4; mt++) {
#pragma unroll
        for (int nt = 0; nt < 4; nt++) {
            const int rb = row0 + wm0 + mt * 16 + grp;
            const int cb = lcol0 + wn0 + nt * 8 + tig * 2;   // even column (local)
#pragma unroll
            for (int half = 0; half < 2; half++) {
                const int r = rb + half * 8;
                const float v0 = acc[mt][nt][half * 2 + 0];
                const float v1 = acc[mt][nt][half * 2 + 1];
                if (mode == 0) {
                    Cout[(size_t)r * DM + cb]     = v0;
                    Cout[(size_t)r * DM + cb + 1] = v1;
                } else if (mode == 3) {
                    const int kv = cb >> 6, d = cb & 63;
                    const size_t base = ((size_t)kv * TT + r) * HD + d;
                    g_V[base]     = v0;
                    g_V[base + 1] = v1;
                } else {
                    const int d = cb & 63;
                    const float cs = freqs[(size_t)r * HD + d];
                    const float sn = freqs[(size_t)TT * HD + (size_t)r * HD + d];
                    const float o0 = v0 * cs - v1 * sn;
                    const float o1 = v1 * cs + v0 * sn;
                    if (mode == 1) {
                        g_Q[(size_t)r * DM + cb]     = o0;
                        g_Q[(size_t)r * DM + cb + 1] = o1;
                    } else {
                        const int kv = cb >> 6;
                        const size_t base = ((size_t)kv * TT + r) * HD + d;
                        g_K[base]     = o0;
                        g_K[base + 1] = o1;
                    }
                }
            }
        }
    }
}

// ---------------------------------------------------------------------------
// Tensor-core flash attention (unchanged from R3).
// ---------------------------------------------------------------------------
__global__ __launch_bounds__(128, 3)
void attn_tc_kernel()
{
    __shared__ __align__(16) float Ks[64][68];
    __shared__ __align__(16) float Vs[64][68];

    const int h   = blockIdx.x;
    const int qb  = (TT / 64 - 1) - blockIdx.y;
    const int kvh = h >> 2;
    const int tid  = threadIdx.x;
    const int lane = tid & 31;
    const int warp = tid >> 5;
    const int wm0  = warp * 16;
    const int grp  = lane >> 2;
    const int tig  = lane & 3;

    const float* kbase = g_K + (size_t)kvh * TT * HD;
    const float* vbase = g_V + (size_t)kvh * TT * HD;

    {
        const float* qsrc = g_Q + ((size_t)(qb * 64)) * DM + h * HD;
#pragma unroll
        for (int i = 0; i < 8; i++) {
            const int j = i * 128 + tid;
            const int row = j >> 4, c4 = (j & 15) * 4;
            float4 v = *(const float4*)(qsrc + (size_t)row * DM + c4);
            Ks[row][c4 + 0] = f2tf32(v.x * 0.125f);
            Ks[row][c4 + 1] = f2tf32(v.y * 0.125f);
            Ks[row][c4 + 2] = f2tf32(v.z * 0.125f);
            Ks[row][c4 + 3] = f2tf32(v.w * 0.125f);
        }
    }
    __syncthreads();

    uint32_t qf[8][4];
#pragma unroll
    for (int ks = 0; ks < 8; ks++) {
        qf[ks][0] = __float_as_uint(Ks[wm0 + grp][8 * ks + tig]);
        qf[ks][1] = __float_as_uint(Ks[wm0 + grp + 8][8 * ks + tig]);
        qf[ks][2] = __float_as_uint(Ks[wm0 + grp][8 * ks + tig + 4]);
        qf[ks][3] = __float_as_uint(Ks[wm0 + grp + 8][8 * ks + tig + 4]);
    }
    __syncthreads();

    float acc[8][4];
#pragma unroll
    for (int nt = 0; nt < 8; nt++)
#pragma unroll
        for (int u = 0; u < 4; u++) acc[nt][u] = 0.f;
    float m0 = -1e30f, m1 = -1e30f, l0 = 0.f, l1 = 0.f;

    const int src0 = (lane & ~3) + (tig >> 1);
    const int src1 = src0 + 2;
    const bool odd = tig & 1;

    for (int kt = 0; kt <= qb; kt++) {
#pragma unroll
        for (int i = 0; i < 8; i++) {
            const int j = i * 128 + tid;
            const int row = j >> 4, c4 = (j & 15) * 4;
            const size_t goff = ((size_t)(kt * 64 + row)) * HD + c4;
            float4 kx = *(const float4*)(kbase + goff);
            float4 vx = *(const float4*)(vbase + goff);
            Ks[row][c4 + 0] = f2tf32(kx.x);
            Ks[row][c4 + 1] = f2tf32(kx.y);
            Ks[row][c4 + 2] = f2tf32(kx.z);
            Ks[row][c4 + 3] = f2tf32(kx.w);
            Vs[row][c4 + 0] = f2tf32(vx.x);
            Vs[row][c4 + 1] = f2tf32(vx.y);
            Vs[row][c4 + 2] = f2tf32(vx.z);
            Vs[row][c4 + 3] = f2tf32(vx.w);
        }
        __syncthreads();

        float s[8][4];
#pragma unroll
        for (int nt = 0; nt < 8; nt++)
#pragma unroll
            for (int u = 0; u < 4; u++) s[nt][u] = 0.f;

#pragma unroll
        for (int ks = 0; ks < 8; ks++) {
#pragma unroll
            for (int nt = 0; nt < 8; nt++) {
                uint32_t b[2];
                b[0] = __float_as_uint(Ks[8 * nt + grp][8 * ks + tig]);
                b[1] = __float_as_uint(Ks[8 * nt + grp][8 * ks + tig + 4]);
                mma_tf32(s[nt], qf[ks], b);
            }
        }

        if (kt == qb) {
            const int r0 = wm0 + grp, r1 = r0 + 8;
#pragma unroll
            for (int nt = 0; nt < 8; nt++) {
                const int c = 8 * nt + 2 * tig;
                if (c > r0)     s[nt][0] = -1e30f;
                if (c + 1 > r0) s[nt][1] = -1e30f;
                if (c > r1)     s[nt][2] = -1e30f;
                if (c + 1 > r1) s[nt][3] = -1e30f;
            }
        }

        float t0 = -1e30f, t1 = -1e30f;
#pragma unroll
        for (int nt = 0; nt < 8; nt++) {
            t0 = fmaxf(t0, fmaxf(s[nt][0], s[nt][1]));
            t1 = fmaxf(t1, fmaxf(s[nt][2], s[nt][3]));
        }
        t0 = fmaxf(t0, __shfl_xor_sync(0xffffffffu, t0, 1));
        t0 = fmaxf(t0, __shfl_xor_sync(0xffffffffu, t0, 2));
        t1 = fmaxf(t1, __shfl_xor_sync(0xffffffffu, t1, 1));
        t1 = fmaxf(t1, __shfl_xor_sync(0xffffffffu, t1, 2));

        const float mn0 = fmaxf(m0, t0), mn1 = fmaxf(m1, t1);
        const float cr0 = __expf(m0 - mn0), cr1 = __expf(m1 - mn1);
        m0 = mn0; m1 = mn1;
        l0 *= cr0; l1 *= cr1;
#pragma unroll
        for (int nt = 0; nt < 8; nt++) {
            acc[nt][0] *= cr0; acc[nt][1] *= cr0;
            acc[nt][2] *= cr1; acc[nt][3] *= cr1;
        }

#pragma unroll
        for (int nt = 0; nt < 8; nt++) {
            float p0 = f2tf32(__expf(s[nt][0] - m0));
            float p1 = f2tf32(__expf(s[nt][1] - m0));
            float p2 = f2tf32(__expf(s[nt][2] - m1));
            float p3 = f2tf32(__expf(s[nt][3] - m1));
            l0 += p0 + p1; l1 += p2 + p3;
            s[nt][0] = p0; s[nt][1] = p1; s[nt][2] = p2; s[nt][3] = p3;
        }

#pragma unroll
        for (int ks = 0; ks < 8; ks++) {
            uint32_t a[4];
            {
                float v0 = __shfl_sync(0xffffffffu, s[ks][0], src0);
                float v1 = __shfl_sync(0xffffffffu, s[ks][1], src0);
                float v2 = __shfl_sync(0xffffffffu, s[ks][2], src0);
                float v3 = __shfl_sync(0xffffffffu, s[ks][3], src0);
                float w0 = __shfl_sync(0xffffffffu, s[ks][0], src1);
                float w1 = __shfl_sync(0xffffffffu, s[ks][1], src1);
                float w2 = __shfl_sync(0xffffffffu, s[ks][2], src1);
                float w3 = __shfl_sync(0xffffffffu, s[ks][3], src1);
                a[0] = __float_as_uint(odd ? v1 : v0);
                a[1] = __float_as_uint(odd ? v3 : v2);
                a[2] = __float_as_uint(odd ? w1 : w0);
                a[3] = __float_as_uint(odd ? w3 : w2);
            }
#pragma unroll
            for (int nt = 0; nt < 8; nt++) {
                uint32_t b[2];
                b[0] = __float_as_uint(Vs[8 * ks + tig][8 * nt + grp]);
                b[1] = __float_as_uint(Vs[8 * ks + tig + 4][8 * nt + grp]);
                mma_tf32(acc[nt], a, b);
            }
        }
        __syncthreads();
    }

    l0 += __shfl_xor_sync(0xffffffffu, l0, 1);
    l0 += __shfl_xor_sync(0xffffffffu, l0, 2);
    l1 += __shfl_xor_sync(0xffffffffu, l1, 1);
    l1 += __shfl_xor_sync(0xffffffffu, l1, 2);
    const float i0 = 1.f / l0, i1 = 1.f / l1;

    const int tq0 = qb * 64 + wm0 + grp;
    float* o0 = g_O + (size_t)tq0 * DM + h * HD;
    float* o1 = o0 + (size_t)8 * DM;
#pragma unroll
    for (int nt = 0; nt < 8; nt++) {
        const int c = 8 * nt + 2 * tig;
        float2 u0 = make_float2(acc[nt][0] * i0, acc[nt][1] * i0);
        float2 u1 = make_float2(acc[nt][2] * i1, acc[nt][3] * i1);
        *(float2*)(o0 + c) = u0;
        *(float2*)(o1 + c) = u1;
    }
}

// ---------------------------------------------------------------------------
extern "C" void kernel_launch(void* const* d_in, const int* in_sizes, int n_in,
                              void* d_out, int out_size)
{
    const float* x     = (const float*)d_in[0];
    const float* freqs = (const float*)d_in[1];
    const float* Wq    = (const float*)d_in[3];
    const float* Wk    = (const float*)d_in[4];
    const float* Wv    = (const float*)d_in[5];
    const float* Wo    = (const float*)d_in[6];
    float* out = (float*)d_out;

    dim3 blk(256);
    // fused Q|K|V projections (+RoPE)
    gemm_tc<true><<<dim3(3072 / 128, TT / 128), blk>>>(x, Wq, Wk, Wv, nullptr, nullptr, freqs);
    // attention
    attn_tc_kernel<<<dim3(NH, TT / 64), dim3(128)>>>();
    // output projection
    gemm_tc<false><<<dim3(DM / 128, TT / 128), blk>>>(nullptr, nullptr, nullptr, nullptr, Wo, out, nullptr);
}

// round 8
// speedup vs baseline: 4.4715x; 1.0643x over previous
#include <cuda_runtime.h>
#include <math.h>
#include <stdint.h>

#define TT   2048
#define DM   2048
#define NH   32
#define NKV  8
#define HD   64

// ---------------- scratch (inputs pre-rounded to tf32) ----------------
__device__ float g_X[TT * DM];          // x, tf32
__device__ float g_Wqkv[DM * 3072];     // [k][ Wq | Wk | Wv ], tf32
__device__ float g_Wo[DM * DM];         // tf32
__device__ float g_Q[TT * DM];          // RoPE'd, tf32
__device__ float g_K[NKV * TT * HD];    // RoPE'd, tf32
__device__ float g_V[NKV * TT * HD];    // tf32
__device__ float g_O[TT * DM];          // attn out, tf32

__device__ __forceinline__ float f2tf32(float x) {
    float y; asm("cvt.rna.tf32.f32 %0, %1;" : "=f"(y) : "f"(x)); return y;
}
__device__ __forceinline__ void mma_tf32(float* d, const uint32_t* a, const uint32_t* b) {
    asm volatile(
        "mma.sync.aligned.m16n8k8.row.col.f32.tf32.tf32.f32 "
        "{%0,%1,%2,%3}, {%4,%5,%6,%7}, {%8,%9}, {%0,%1,%2,%3};"
        : "+f"(d[0]), "+f"(d[1]), "+f"(d[2]), "+f"(d[3])
        : "r"(a[0]), "r"(a[1]), "r"(a[2]), "r"(a[3]), "r"(b[0]), "r"(b[1]));
}
__device__ __forceinline__ uint32_t smem_u32(const void* p) {
    uint32_t a;
    asm("{ .reg .u64 t; cvta.to.shared.u64 t, %1; cvt.u32.u64 %0, t; }" : "=r"(a) : "l"(p));
    return a;
}
#define CPA16(dst, src) asm volatile("cp.async.cg.shared.global [%0], [%1], 16;" :: "r"(dst), "l"(src))
#define CP_COMMIT()     asm volatile("cp.async.commit_group;" ::: "memory")
#define CP_WAIT(n)      asm volatile("cp.async.wait_group %0;" :: "n"(n) : "memory")

// ---------------------------------------------------------------------------
// Pre-pass: elementwise tf32 round into a device-global destination.
// DST: 0 -> g_X, 1 -> g_Wqkv (dstN=3072, col0 per segment), 2 -> g_Wo.
// (Destination chosen in DEVICE code — device globals must never be passed
//  as kernel arguments from host.)
// ---------------------------------------------------------------------------
template <int DST>
__global__ __launch_bounds__(256)
void conv_w(const float* __restrict__ src, int Nsrc, int dstN, int col0)
{
    float* dst = (DST == 0) ? g_X : (DST == 1) ? g_Wqkv : g_Wo;
    const int i = blockIdx.x * 256 + threadIdx.x;
    const int nc4 = Nsrc >> 2;
    const int row = i / nc4, c4 = (i - row * nc4) * 4;
    float4 v = *(const float4*)(src + (size_t)row * Nsrc + c4);
    v.x = f2tf32(v.x); v.y = f2tf32(v.y); v.z = f2tf32(v.z); v.w = f2tf32(v.w);
    *(float4*)(dst + (size_t)row * dstN + col0 + c4) = v;
}

// ---------------------------------------------------------------------------
// TF32 GEMM, 128x128x32 tiles, 256 thr, cp.async double-buffered.
// QKV=true : A=g_X, B=g_Wqkv (N=3072), epilogue RoPE->g_Q/g_K, ->g_V (tf32)
// QKV=false: A=g_O, B=g_Wo (N=2048), plain fp32 -> Cout
// ---------------------------------------------------------------------------
template <bool QKV>
__global__ __launch_bounds__(256)
void gemm_tc(float* __restrict__ Cout, const float* __restrict__ freqs)
{
    __shared__ __align__(16) float As[2][128][36];
    __shared__ __align__(16) float Bs[2][32][132];

    const int tid  = threadIdx.x;
    const int lane = tid & 31;
    const int warp = tid >> 5;
    const int wm0  = (warp & 1) * 64;
    const int wn0  = (warp >> 1) * 32;
    const int row0 = blockIdx.y * 128;
    const int col0g = blockIdx.x * 128;
    const int N = QKV ? 3072 : 2048;

    const float* A = QKV ? g_X : g_O;
    const float* B = QKV ? g_Wqkv : g_Wo;

    const int arow = tid >> 3;
    const int akc  = (tid & 7) * 4;
    const int bkr  = tid >> 5;
    const int bc   = lane * 4;

    const float* aSrc = A + (size_t)(row0 + arow) * DM + akc;
    const float* bSrc = B + (size_t)bkr * N + col0g + bc;
    const uint32_t aDst = smem_u32(&As[0][arow][akc]);
    const uint32_t bDst = smem_u32(&Bs[0][bkr][bc]);
    const uint32_t aBufStride = 128 * 36 * 4;
    const uint32_t bBufStride = 32 * 132 * 4;

    // prefetch slab 0
#pragma unroll
    for (int i = 0; i < 4; i++) CPA16(aDst + i * 32 * 144, aSrc + (size_t)(32 * i) * DM);
#pragma unroll
    for (int i = 0; i < 4; i++) CPA16(bDst + i * 8 * 528, bSrc + (size_t)(8 * i) * N);
    CP_COMMIT();

    float acc[4][4][4];
#pragma unroll
    for (int mt = 0; mt < 4; mt++)
#pragma unroll
        for (int nt = 0; nt < 4; nt++)
#pragma unroll
            for (int u = 0; u < 4; u++) acc[mt][nt][u] = 0.f;

    const int grp = lane >> 2;
    const int tig = lane & 3;

    for (int s = 0; s < 64; s++) {
        const int cur = s & 1;
        if (s + 1 < 64) {
            const int nb = (s + 1) & 1;
            const int k0 = (s + 1) * 32;
#pragma unroll
            for (int i = 0; i < 4; i++)
                CPA16(aDst + nb * aBufStride + i * 32 * 144, aSrc + (size_t)k0 + (size_t)(32 * i) * DM);
#pragma unroll
            for (int i = 0; i < 4; i++)
                CPA16(bDst + nb * bBufStride + i * 8 * 528, bSrc + (size_t)(k0 + 8 * i) * N);
            CP_COMMIT();
            CP_WAIT(1);
        } else {
            CP_WAIT(0);
        }
        __syncthreads();

#pragma unroll
        for (int ks = 0; ks < 4; ks++) {
            const int kc = ks * 8 + tig;
            uint32_t afr[4][4], bfr[4][2];
#pragma unroll
            for (int mt = 0; mt < 4; mt++) {
                const int r = wm0 + mt * 16 + grp;
                afr[mt][0] = __float_as_uint(As[cur][r][kc]);
                afr[mt][1] = __float_as_uint(As[cur][r + 8][kc]);
                afr[mt][2] = __float_as_uint(As[cur][r][kc + 4]);
                afr[mt][3] = __float_as_uint(As[cur][r + 8][kc + 4]);
            }
#pragma unroll
            for (int nt = 0; nt < 4; nt++) {
                const int c = wn0 + nt * 8 + grp;
                bfr[nt][0] = __float_as_uint(Bs[cur][ks * 8 + tig][c]);
                bfr[nt][1] = __float_as_uint(Bs[cur][ks * 8 + tig + 4][c]);
            }
#pragma unroll
            for (int mt = 0; mt < 4; mt++)
#pragma unroll
                for (int nt = 0; nt < 4; nt++)
                    mma_tf32(acc[mt][nt], afr[mt], bfr[nt]);
        }
        __syncthreads();
    }

    // epilogue
#pragma unroll
    for (int mt = 0; mt < 4; mt++) {
#pragma unroll
        for (int nt = 0; nt < 4; nt++) {
            const int rb = row0 + wm0 + mt * 16 + grp;
            const int cb = col0g + wn0 + nt * 8 + tig * 2;   // even global col
#pragma unroll
            for (int half = 0; half < 2; half++) {
                const int r = rb + half * 8;
                const float v0 = acc[mt][nt][half * 2 + 0];
                const float v1 = acc[mt][nt][half * 2 + 1];
                if (!QKV) {
                    *(float2*)(Cout + (size_t)r * DM + cb) = make_float2(v0, v1);
                } else if (cb >= 2560) {   // V
                    const int lc = cb - 2560;
                    const int kv = lc >> 6, d = lc & 63;
                    *(float2*)(g_V + ((size_t)kv * TT + r) * HD + d) =
                        make_float2(f2tf32(v0), f2tf32(v1));
                } else {                   // Q or K: RoPE
                    const int lc = (cb >= 2048) ? cb - 2048 : cb;
                    const int d = lc & 63;
                    const float cs = freqs[(size_t)r * HD + d];
                    const float sn = freqs[(size_t)TT * HD + (size_t)r * HD + d];
                    const float o0 = f2tf32(v0 * cs - v1 * sn);
                    const float o1 = f2tf32(v1 * cs + v0 * sn);
                    if (cb < 2048) {
                        *(float2*)(g_Q + (size_t)r * DM + cb) = make_float2(o0, o1);
                    } else {
                        const int kv = lc >> 6;
                        *(float2*)(g_K + ((size_t)kv * TT + r) * HD + d) = make_float2(o0, o1);
                    }
                }
            }
        }
    }
}

// ---------------------------------------------------------------------------
// Tensor-core flash attention, cp.async double-buffered K/V tiles.
// CTA: 1 head x 64 queries, 4 warps. Inputs already tf32.
// ---------------------------------------------------------------------------
__global__ __launch_bounds__(128, 3)
void attn_tc_kernel()
{
    __shared__ __align__(16) float Ks[2][64][68];
    __shared__ __align__(16) float Vs[2][64][68];

    const int h   = blockIdx.x;
    const int qb  = (TT / 64 - 1) - blockIdx.y;
    const int kvh = h >> 2;
    const int tid  = threadIdx.x;
    const int lane = tid & 31;
    const int warp = tid >> 5;
    const int wm0  = warp * 16;
    const int grp  = lane >> 2;
    const int tig  = lane & 3;

    const float* kbase = g_K + (size_t)kvh * TT * HD;
    const float* vbase = g_V + (size_t)kvh * TT * HD;

    // ---- stage Q (x 1/8 scale; exact on tf32 values) through Ks[0] ----
    {
        const float* qsrc = g_Q + ((size_t)(qb * 64)) * DM + h * HD;
#pragma unroll
        for (int i = 0; i < 8; i++) {
            const int j = i * 128 + tid;
            const int row = j >> 4, c4 = (j & 15) * 4;
            float4 v = *(const float4*)(qsrc + (size_t)row * DM + c4);
            Ks[0][row][c4 + 0] = v.x * 0.125f;
            Ks[0][row][c4 + 1] = v.y * 0.125f;
            Ks[0][row][c4 + 2] = v.z * 0.125f;
            Ks[0][row][c4 + 3] = v.w * 0.125f;
        }
    }
    __syncthreads();

    uint32_t qf[8][4];
#pragma unroll
    for (int ks = 0; ks < 8; ks++) {
        qf[ks][0] = __float_as_uint(Ks[0][wm0 + grp][8 * ks + tig]);
        qf[ks][1] = __float_as_uint(Ks[0][wm0 + grp + 8][8 * ks + tig]);
        qf[ks][2] = __float_as_uint(Ks[0][wm0 + grp][8 * ks + tig + 4]);
        qf[ks][3] = __float_as_uint(Ks[0][wm0 + grp + 8][8 * ks + tig + 4]);
    }
    __syncthreads();

    // cp.async mapping: 8 chunks K + 8 chunks V per thread per 64x64 tile
    const int krow = tid >> 4;          // 0..7, rows krow+8*i
    const int kc4  = (tid & 15) * 4;    // 0..60
    const uint32_t kDst = smem_u32(&Ks[0][krow][kc4]);
    const uint32_t vDst = smem_u32(&Vs[0][krow][kc4]);
    const uint32_t bufStride = 64 * 68 * 4;
    const float* kSrc = kbase + (size_t)krow * HD + kc4;
    const float* vSrc = vbase + (size_t)krow * HD + kc4;

    // prefetch tile 0 into buf 0
#pragma unroll
    for (int i = 0; i < 8; i++) CPA16(kDst + i * 8 * 272, kSrc + (size_t)(8 * i) * HD);
#pragma unroll
    for (int i = 0; i < 8; i++) CPA16(vDst + i * 8 * 272, vSrc + (size_t)(8 * i) * HD);
    CP_COMMIT();

    float acc[8][4];
#pragma unroll
    for (int nt = 0; nt < 8; nt++)
#pragma unroll
        for (int u = 0; u < 4; u++) acc[nt][u] = 0.f;
    float m0 = -1e30f, m1 = -1e30f, l0 = 0.f, l1 = 0.f;

    const int src0 = (lane & ~3) + (tig >> 1);
    const int src1 = src0 + 2;
    const bool odd = tig & 1;

    for (int kt = 0; kt <= qb; kt++) {
        const int cur = kt & 1;
        if (kt < qb) {
            const int nb = (kt + 1) & 1;
            const size_t off = (size_t)(kt + 1) * 64 * HD;
#pragma unroll
            for (int i = 0; i < 8; i++)
                CPA16(kDst + nb * bufStride + i * 8 * 272, kSrc + off + (size_t)(8 * i) * HD);
#pragma unroll
            for (int i = 0; i < 8; i++)
                CPA16(vDst + nb * bufStride + i * 8 * 272, vSrc + off + (size_t)(8 * i) * HD);
            CP_COMMIT();
            CP_WAIT(1);
        } else {
            CP_WAIT(0);
        }
        __syncthreads();

        // ---- S = Q K^T ----
        float s[8][4];
#pragma unroll
        for (int nt = 0; nt < 8; nt++)
#pragma unroll
            for (int u = 0; u < 4; u++) s[nt][u] = 0.f;

#pragma unroll
        for (int ks = 0; ks < 8; ks++) {
#pragma unroll
            for (int nt = 0; nt < 8; nt++) {
                uint32_t b[2];
                b[0] = __float_as_uint(Ks[cur][8 * nt + grp][8 * ks + tig]);
                b[1] = __float_as_uint(Ks[cur][8 * nt + grp][8 * ks + tig + 4]);
                mma_tf32(s[nt], qf[ks], b);
            }
        }

        if (kt == qb) {
            const int r0 = wm0 + grp, r1 = r0 + 8;
#pragma unroll
            for (int nt = 0; nt < 8; nt++) {
                const int c = 8 * nt + 2 * tig;
                if (c > r0)     s[nt][0] = -1e30f;
                if (c + 1 > r0) s[nt][1] = -1e30f;
                if (c > r1)     s[nt][2] = -1e30f;
                if (c + 1 > r1) s[nt][3] = -1e30f;
            }
        }

        // ---- online softmax ----
        float t0 = -1e30f, t1 = -1e30f;
#pragma unroll
        for (int nt = 0; nt < 8; nt++) {
            t0 = fmaxf(t0, fmaxf(s[nt][0], s[nt][1]));
            t1 = fmaxf(t1, fmaxf(s[nt][2], s[nt][3]));
        }
        t0 = fmaxf(t0, __shfl_xor_sync(0xffffffffu, t0, 1));
        t0 = fmaxf(t0, __shfl_xor_sync(0xffffffffu, t0, 2));
        t1 = fmaxf(t1, __shfl_xor_sync(0xffffffffu, t1, 1));
        t1 = fmaxf(t1, __shfl_xor_sync(0xffffffffu, t1, 2));

        const float mn0 = fmaxf(m0, t0), mn1 = fmaxf(m1, t1);
        const float cr0 = __expf(m0 - mn0), cr1 = __expf(m1 - mn1);
        m0 = mn0; m1 = mn1;
        l0 *= cr0; l1 *= cr1;
#pragma unroll
        for (int nt = 0; nt < 8; nt++) {
            acc[nt][0] *= cr0; acc[nt][1] *= cr0;
            acc[nt][2] *= cr1; acc[nt][3] *= cr1;
        }

#pragma unroll
        for (int nt = 0; nt < 8; nt++) {
            float p0 = f2tf32(__expf(s[nt][0] - m0));
            float p1 = f2tf32(__expf(s[nt][1] - m0));
            float p2 = f2tf32(__expf(s[nt][2] - m1));
            float p3 = f2tf32(__expf(s[nt][3] - m1));
            l0 += p0 + p1; l1 += p2 + p3;
            s[nt][0] = p0; s[nt][1] = p1; s[nt][2] = p2; s[nt][3] = p3;
        }

        // ---- O += P V ----
#pragma unroll
        for (int ks = 0; ks < 8; ks++) {
            uint32_t a[4];
            {
                float v0 = __shfl_sync(0xffffffffu, s[ks][0], src0);
                float v1 = __shfl_sync(0xffffffffu, s[ks][1], src0);
                float v2 = __shfl_sync(0xffffffffu, s[ks][2], src0);
                float v3 = __shfl_sync(0xffffffffu, s[ks][3], src0);
                float w0 = __shfl_sync(0xffffffffu, s[ks][0], src1);
                float w1 = __shfl_sync(0xffffffffu, s[ks][1], src1);
                float w2 = __shfl_sync(0xffffffffu, s[ks][2], src1);
                float w3 = __shfl_sync(0xffffffffu, s[ks][3], src1);
                a[0] = __float_as_uint(odd ? v1 : v0);
                a[1] = __float_as_uint(odd ? v3 : v2);
                a[2] = __float_as_uint(odd ? w1 : w0);
                a[3] = __float_as_uint(odd ? w3 : w2);
            }
#pragma unroll
            for (int nt = 0; nt < 8; nt++) {
                uint32_t b[2];
                b[0] = __float_as_uint(Vs[cur][8 * ks + tig][8 * nt + grp]);
                b[1] = __float_as_uint(Vs[cur][8 * ks + tig + 4][8 * nt + grp]);
                mma_tf32(acc[nt], a, b);
            }
        }
        __syncthreads();
    }

    l0 += __shfl_xor_sync(0xffffffffu, l0, 1);
    l0 += __shfl_xor_sync(0xffffffffu, l0, 2);
    l1 += __shfl_xor_sync(0xffffffffu, l1, 1);
    l1 += __shfl_xor_sync(0xffffffffu, l1, 2);
    const float i0 = 1.f / l0, i1 = 1.f / l1;

    const int tq0 = qb * 64 + wm0 + grp;
    float* o0 = g_O + (size_t)tq0 * DM + h * HD;
    float* o1 = o0 + (size_t)8 * DM;
#pragma unroll
    for (int nt = 0; nt < 8; nt++) {
        const int c = 8 * nt + 2 * tig;
        *(float2*)(o0 + c) = make_float2(f2tf32(acc[nt][0] * i0), f2tf32(acc[nt][1] * i0));
        *(float2*)(o1 + c) = make_float2(f2tf32(acc[nt][2] * i1), f2tf32(acc[nt][3] * i1));
    }
}

// ---------------------------------------------------------------------------
extern "C" void kernel_launch(void* const* d_in, const int* in_sizes, int n_in,
                              void* d_out, int out_size)
{
    const float* x     = (const float*)d_in[0];
    const float* freqs = (const float*)d_in[1];
    const float* Wq    = (const float*)d_in[3];
    const float* Wk    = (const float*)d_in[4];
    const float* Wv    = (const float*)d_in[5];
    const float* Wo    = (const float*)d_in[6];
    float* out = (float*)d_out;

    // pre-passes: tf32 rounding (+ QKV weight concat); dst picked device-side
    conv_w<0><<<TT * DM / 1024, 256>>>(x, DM, DM, 0);
    conv_w<1><<<DM * 2048 / 1024, 256>>>(Wq, 2048, 3072, 0);
    conv_w<1><<<DM * 512 / 1024, 256>>>(Wk, 512, 3072, 2048);
    conv_w<1><<<DM * 512 / 1024, 256>>>(Wv, 512, 3072, 2560);
    conv_w<2><<<DM * 2048 / 1024, 256>>>(Wo, 2048, 2048, 0);

    // fused QKV projections (+RoPE)
    gemm_tc<true><<<dim3(3072 / 128, TT / 128), 256>>>(nullptr, freqs);
    // attention
    attn_tc_kernel<<<dim3(NH, TT / 64), dim3(128)>>>();
    // output projection
    gemm_tc<false><<<dim3(DM / 128, TT / 128), 256>>>(out, nullptr);
}

// round 9
// speedup vs baseline: 4.8878x; 1.0931x over previous
#include <cuda_runtime.h>
#include <math.h>
#include <stdint.h>

#define TT   2048
#define DM   2048
#define NH   32
#define NKV  8
#define HD   64

// ---------------- scratch ----------------
// k-dim of X / O / W is stored PERMUTED within each 16-group:
//   phys = 4*(k&3) + 2*((k>>3)&1) + ((k>>2)&1)
// so one LDS.128 yields mma fragments for two k-steps.
__device__ float g_X[TT * DM];          // x, tf32, k-permuted
__device__ float g_WT[5120 * DM];       // [n][k] transposed+permuted tf32:
                                        // rows [0,2048)=Wq [2048,2560)=Wk [2560,3072)=Wv [3072,5120)=Wo
__device__ float g_Q[TT * DM];          // RoPE'd, tf32 (logical layout)
__device__ float g_K[NKV * TT * HD];    // RoPE'd, tf32 (logical)
__device__ float g_V[NKV * TT * HD];    // tf32 (logical)
__device__ float g_O[TT * DM];          // attn out, tf32, k-permuted

__device__ __forceinline__ int perm16(int j) {
    return 4 * (j & 3) + 2 * ((j >> 3) & 1) + ((j >> 2) & 1);
}
__device__ __forceinline__ float f2tf32(float x) {
    float y; asm("cvt.rna.tf32.f32 %0, %1;" : "=f"(y) : "f"(x)); return y;
}
__device__ __forceinline__ void mma_tf32(float* d, const uint32_t* a, const uint32_t* b) {
    asm volatile(
        "mma.sync.aligned.m16n8k8.row.col.f32.tf32.tf32.f32 "
        "{%0,%1,%2,%3}, {%4,%5,%6,%7}, {%8,%9}, {%0,%1,%2,%3};"
        : "+f"(d[0]), "+f"(d[1]), "+f"(d[2]), "+f"(d[3])
        : "r"(a[0]), "r"(a[1]), "r"(a[2]), "r"(a[3]), "r"(b[0]), "r"(b[1]));
}
__device__ __forceinline__ uint32_t smem_u32(const void* p) {
    uint32_t a;
    asm("{ .reg .u64 t; cvta.to.shared.u64 t, %1; cvt.u32.u64 %0, t; }" : "=r"(a) : "l"(p));
    return a;
}
#define CPA16(dst, src) asm volatile("cp.async.cg.shared.global [%0], [%1], 16;" :: "r"(dst), "l"(src))
#define CP_COMMIT()     asm volatile("cp.async.commit_group;" ::: "memory")
#define CP_WAIT(n)      asm volatile("cp.async.wait_group %0;" :: "n"(n) : "memory")

// ---------------------------------------------------------------------------
// Pre-pass A: x -> g_X, tf32 + k-perm within 16-groups (no transpose).
// Each thread handles 16 consecutive logical k of one row.
// out quad q = { in[q], in[q+4], in[q+8], in[q+12] }  (== perm16)
// ---------------------------------------------------------------------------
__global__ __launch_bounds__(256)
void conv_x(const float* __restrict__ src)
{
    const size_t base = ((size_t)blockIdx.x * 256 + threadIdx.x) * 16;
    float4 v0 = *(const float4*)(src + base + 0);
    float4 v1 = *(const float4*)(src + base + 4);
    float4 v2 = *(const float4*)(src + base + 8);
    float4 v3 = *(const float4*)(src + base + 12);
    float4 o;
    o = make_float4(f2tf32(v0.x), f2tf32(v1.x), f2tf32(v2.x), f2tf32(v3.x));
    *(float4*)(g_X + base + 0) = o;
    o = make_float4(f2tf32(v0.y), f2tf32(v1.y), f2tf32(v2.y), f2tf32(v3.y));
    *(float4*)(g_X + base + 4) = o;
    o = make_float4(f2tf32(v0.z), f2tf32(v1.z), f2tf32(v2.z), f2tf32(v3.z));
    *(float4*)(g_X + base + 8) = o;
    o = make_float4(f2tf32(v0.w), f2tf32(v1.w), f2tf32(v2.w), f2tf32(v3.w));
    *(float4*)(g_X + base + 12) = o;
}

// ---------------------------------------------------------------------------
// Pre-pass B: W[k][n] -> g_WT[rowbase+n][k], tf32, k permuted within 16-groups.
// 32x32 smem-tile transpose; 256 threads = (tx 0..31, ty 0..7).
// ---------------------------------------------------------------------------
__global__ __launch_bounds__(256)
void conv_wt(const float* __restrict__ src, int N, int rowbase)
{
    __shared__ float tile[32][33];
    const int tx = threadIdx.x & 31, ty = threadIdx.x >> 5;
    const int n0 = blockIdx.x * 32, k0 = blockIdx.y * 32;
#pragma unroll
    for (int i = 0; i < 4; i++)
        tile[ty + 8 * i][tx] = src[(size_t)(k0 + ty + 8 * i) * N + n0 + tx];
    __syncthreads();
    const int pk = (tx & 16) | perm16(tx & 15);   // permuted k-local
#pragma unroll
    for (int i = 0; i < 4; i++) {
        const int nl = ty + 8 * i;
        g_WT[(size_t)(rowbase + n0 + nl) * DM + k0 + pk] = f2tf32(tile[tx][nl]);
    }
}

// ---------------------------------------------------------------------------
// TF32 GEMM, 128x128x32 tiles, 256 thr, cp.async double-buffered,
// LDS.128 fragment loads (XOR-swizzled smem, stride 32 words, no pad).
// QKV=true : A=g_X, B=g_WT rows [0,3072), epilogue RoPE->g_Q/g_K, ->g_V
// QKV=false: A=g_O, B=g_WT rows [3072,5120), plain fp32 -> Cout
// ---------------------------------------------------------------------------
template <bool QKV>
__global__ __launch_bounds__(256)
void gemm_tc(float* __restrict__ Cout, const float* __restrict__ freqs)
{
    __shared__ __align__(16) float As[2][128][32];
    __shared__ __align__(16) float Bs[2][128][32];

    const int tid  = threadIdx.x;
    const int lane = tid & 31;
    const int warp = tid >> 5;
    const int wm0  = (warp & 1) * 64;
    const int wn0  = (warp >> 1) * 32;
    const int grp  = lane >> 2;
    const int tig  = lane & 3;
    const int row0 = blockIdx.y * 128;
    const int col0g = blockIdx.x * 128;

    const float* A = QKV ? g_X : g_O;
    const float* Bw = g_WT + (size_t)((QKV ? 0 : 3072) + col0g) * DM;

    const uint32_t aBase = smem_u32(&As[0][0][0]);
    const uint32_t bBase = smem_u32(&Bs[0][0][0]);

    // staging: 4 iters x 256 thr = 1024 chunks per tile; row = id>>3, chunk = id&7
    const int st = tid & 7;                     // logical chunk
    const float* Aptr = A + (size_t)row0 * DM + st * 4;
    const float* Bptr = Bw + st * 4;

#define STAGE(buf, k0)                                                        \
    {                                                                         \
        _Pragma("unroll")                                                     \
        for (int it = 0; it < 4; it++) {                                      \
            const int rw = it * 32 + (tid >> 3);                              \
            const uint32_t doff = (uint32_t)(buf) * 16384u + rw * 128u +      \
                                  ((uint32_t)(st ^ ((rw & 1) << 2))) * 16u;   \
            CPA16(aBase + doff, Aptr + (size_t)rw * DM + (k0));               \
            CPA16(bBase + doff, Bptr + (size_t)rw * DM + (k0));               \
        }                                                                     \
    }

    STAGE(0, 0);
    CP_COMMIT();

    float acc[4][4][4];
#pragma unroll
    for (int mt = 0; mt < 4; mt++)
#pragma unroll
        for (int nt = 0; nt < 4; nt++)
#pragma unroll
            for (int u = 0; u < 4; u++) acc[mt][nt][u] = 0.f;

    const int par = (grp & 1) << 2;   // row-parity XOR for fragment quads

    for (int s = 0; s < 64; s++) {
        const int cur = s & 1;
        if (s + 1 < 64) {
            STAGE((s + 1) & 1, (s + 1) * 32);
            CP_COMMIT();
            CP_WAIT(1);
        } else {
            CP_WAIT(0);
        }
        __syncthreads();

#pragma unroll
        for (int c = 0; c < 2; c++) {
            const int q = (((c << 2) + tig) ^ par) << 2;   // word offset of quad
            float4 Bf[4];
#pragma unroll
            for (int nt = 0; nt < 4; nt++)
                Bf[nt] = *(const float4*)&Bs[cur][wn0 + nt * 8 + grp][q];
#pragma unroll
            for (int mt = 0; mt < 4; mt++) {
                const int r = wm0 + mt * 16 + grp;
                float4 A0 = *(const float4*)&As[cur][r][q];
                float4 A1 = *(const float4*)&As[cur][r + 8][q];
                uint32_t ae[4] = {__float_as_uint(A0.x), __float_as_uint(A1.x),
                                  __float_as_uint(A0.y), __float_as_uint(A1.y)};
                uint32_t ao[4] = {__float_as_uint(A0.z), __float_as_uint(A1.z),
                                  __float_as_uint(A0.w), __float_as_uint(A1.w)};
#pragma unroll
                for (int nt = 0; nt < 4; nt++) {
                    uint32_t be[2] = {__float_as_uint(Bf[nt].x), __float_as_uint(Bf[nt].y)};
                    mma_tf32(acc[mt][nt], ae, be);
                }
#pragma unroll
                for (int nt = 0; nt < 4; nt++) {
                    uint32_t bo[2] = {__float_as_uint(Bf[nt].z), __float_as_uint(Bf[nt].w)};
                    mma_tf32(acc[mt][nt], ao, bo);
                }
            }
        }
        __syncthreads();
    }
#undef STAGE

    // epilogue (output columns are logical; k-perm does not affect them)
#pragma unroll
    for (int mt = 0; mt < 4; mt++) {
#pragma unroll
        for (int nt = 0; nt < 4; nt++) {
            const int rb = row0 + wm0 + mt * 16 + grp;
            const int cb = col0g + wn0 + nt * 8 + tig * 2;
#pragma unroll
            for (int half = 0; half < 2; half++) {
                const int r = rb + half * 8;
                const float v0 = acc[mt][nt][half * 2 + 0];
                const float v1 = acc[mt][nt][half * 2 + 1];
                if (!QKV) {
                    *(float2*)(Cout + (size_t)r * DM + cb) = make_float2(v0, v1);
                } else if (cb >= 2560) {   // V
                    const int lc = cb - 2560;
                    const int kv = lc >> 6, d = lc & 63;
                    *(float2*)(g_V + ((size_t)kv * TT + r) * HD + d) =
                        make_float2(f2tf32(v0), f2tf32(v1));
                } else {                   // Q or K: RoPE
                    const int lc = (cb >= 2048) ? cb - 2048 : cb;
                    const int d = lc & 63;
                    const float cs = freqs[(size_t)r * HD + d];
                    const float sn = freqs[(size_t)TT * HD + (size_t)r * HD + d];
                    const float o0 = f2tf32(v0 * cs - v1 * sn);
                    const float o1 = f2tf32(v1 * cs + v0 * sn);
                    if (cb < 2048) {
                        *(float2*)(g_Q + (size_t)r * DM + cb) = make_float2(o0, o1);
                    } else {
                        const int kv = lc >> 6;
                        *(float2*)(g_K + ((size_t)kv * TT + r) * HD + d) = make_float2(o0, o1);
                    }
                }
            }
        }
    }
}

// ---------------------------------------------------------------------------
// Tensor-core flash attention, cp.async double-buffered K/V tiles.
// Unchanged from R8 except the epilogue writes g_O k-PERMUTED (tf32).
// ---------------------------------------------------------------------------
__global__ __launch_bounds__(128, 3)
void attn_tc_kernel()
{
    __shared__ __align__(16) float Ks[2][64][68];
    __shared__ __align__(16) float Vs[2][64][68];

    const int h   = blockIdx.x;
    const int qb  = (TT / 64 - 1) - blockIdx.y;
    const int kvh = h >> 2;
    const int tid  = threadIdx.x;
    const int lane = tid & 31;
    const int warp = tid >> 5;
    const int wm0  = warp * 16;
    const int grp  = lane >> 2;
    const int tig  = lane & 3;

    const float* kbase = g_K + (size_t)kvh * TT * HD;
    const float* vbase = g_V + (size_t)kvh * TT * HD;

    {
        const float* qsrc = g_Q + ((size_t)(qb * 64)) * DM + h * HD;
#pragma unroll
        for (int i = 0; i < 8; i++) {
            const int j = i * 128 + tid;
            const int row = j >> 4, c4 = (j & 15) * 4;
            float4 v = *(const float4*)(qsrc + (size_t)row * DM + c4);
            Ks[0][row][c4 + 0] = v.x * 0.125f;
            Ks[0][row][c4 + 1] = v.y * 0.125f;
            Ks[0][row][c4 + 2] = v.z * 0.125f;
            Ks[0][row][c4 + 3] = v.w * 0.125f;
        }
    }
    __syncthreads();

    uint32_t qf[8][4];
#pragma unroll
    for (int ks = 0; ks < 8; ks++) {
        qf[ks][0] = __float_as_uint(Ks[0][wm0 + grp][8 * ks + tig]);
        qf[ks][1] = __float_as_uint(Ks[0][wm0 + grp + 8][8 * ks + tig]);
        qf[ks][2] = __float_as_uint(Ks[0][wm0 + grp][8 * ks + tig + 4]);
        qf[ks][3] = __float_as_uint(Ks[0][wm0 + grp + 8][8 * ks + tig + 4]);
    }
    __syncthreads();

    const int krow = tid >> 4;
    const int kc4  = (tid & 15) * 4;
    const uint32_t kDst = smem_u32(&Ks[0][krow][kc4]);
    const uint32_t vDst = smem_u32(&Vs[0][krow][kc4]);
    const uint32_t bufStride = 64 * 68 * 4;
    const float* kSrc = kbase + (size_t)krow * HD + kc4;
    const float* vSrc = vbase + (size_t)krow * HD + kc4;

#pragma unroll
    for (int i = 0; i < 8; i++) CPA16(kDst + i * 8 * 272, kSrc + (size_t)(8 * i) * HD);
#pragma unroll
    for (int i = 0; i < 8; i++) CPA16(vDst + i * 8 * 272, vSrc + (size_t)(8 * i) * HD);
    CP_COMMIT();

    float acc[8][4];
#pragma unroll
    for (int nt = 0; nt < 8; nt++)
#pragma unroll
        for (int u = 0; u < 4; u++) acc[nt][u] = 0.f;
    float m0 = -1e30f, m1 = -1e30f, l0 = 0.f, l1 = 0.f;

    const int src0 = (lane & ~3) + (tig >> 1);
    const int src1 = src0 + 2;
    const bool odd = tig & 1;

    for (int kt = 0; kt <= qb; kt++) {
        const int cur = kt & 1;
        if (kt < qb) {
            const int nb = (kt + 1) & 1;
            const size_t off = (size_t)(kt + 1) * 64 * HD;
#pragma unroll
            for (int i = 0; i < 8; i++)
                CPA16(kDst + nb * bufStride + i * 8 * 272, kSrc + off + (size_t)(8 * i) * HD);
#pragma unroll
            for (int i = 0; i < 8; i++)
                CPA16(vDst + nb * bufStride + i * 8 * 272, vSrc + off + (size_t)(8 * i) * HD);
            CP_COMMIT();
            CP_WAIT(1);
        } else {
            CP_WAIT(0);
        }
        __syncthreads();

        float s[8][4];
#pragma unroll
        for (int nt = 0; nt < 8; nt++)
#pragma unroll
            for (int u = 0; u < 4; u++) s[nt][u] = 0.f;

#pragma unroll
        for (int ks = 0; ks < 8; ks++) {
#pragma unroll
            for (int nt = 0; nt < 8; nt++) {
                uint32_t b[2];
                b[0] = __float_as_uint(Ks[cur][8 * nt + grp][8 * ks + tig]);
                b[1] = __float_as_uint(Ks[cur][8 * nt + grp][8 * ks + tig + 4]);
                mma_tf32(s[nt], qf[ks], b);
            }
        }

        if (kt == qb) {
            const int r0 = wm0 + grp, r1 = r0 + 8;
#pragma unroll
            for (int nt = 0; nt < 8; nt++) {
                const int c = 8 * nt + 2 * tig;
                if (c > r0)     s[nt][0] = -1e30f;
                if (c + 1 > r0) s[nt][1] = -1e30f;
                if (c > r1)     s[nt][2] = -1e30f;
                if (c + 1 > r1) s[nt][3] = -1e30f;
            }
        }

        float t0 = -1e30f, t1 = -1e30f;
#pragma unroll
        for (int nt = 0; nt < 8; nt++) {
            t0 = fmaxf(t0, fmaxf(s[nt][0], s[nt][1]));
            t1 = fmaxf(t1, fmaxf(s[nt][2], s[nt][3]));
        }
        t0 = fmaxf(t0, __shfl_xor_sync(0xffffffffu, t0, 1));
        t0 = fmaxf(t0, __shfl_xor_sync(0xffffffffu, t0, 2));
        t1 = fmaxf(t1, __shfl_xor_sync(0xffffffffu, t1, 1));
        t1 = fmaxf(t1, __shfl_xor_sync(0xffffffffu, t1, 2));

        const float mn0 = fmaxf(m0, t0), mn1 = fmaxf(m1, t1);
        const float cr0 = __expf(m0 - mn0), cr1 = __expf(m1 - mn1);
        m0 = mn0; m1 = mn1;
        l0 *= cr0; l1 *= cr1;
#pragma unroll
        for (int nt = 0; nt < 8; nt++) {
            acc[nt][0] *= cr0; acc[nt][1] *= cr0;
            acc[nt][2] *= cr1; acc[nt][3] *= cr1;
        }

#pragma unroll
        for (int nt = 0; nt < 8; nt++) {
            float p0 = f2tf32(__expf(s[nt][0] - m0));
            float p1 = f2tf32(__expf(s[nt][1] - m0));
            float p2 = f2tf32(__expf(s[nt][2] - m1));
            float p3 = f2tf32(__expf(s[nt][3] - m1));
            l0 += p0 + p1; l1 += p2 + p3;
            s[nt][0] = p0; s[nt][1] = p1; s[nt][2] = p2; s[nt][3] = p3;
        }

#pragma unroll
        for (int ks = 0; ks < 8; ks++) {
            uint32_t a[4];
            {
                float v0 = __shfl_sync(0xffffffffu, s[ks][0], src0);
                float v1 = __shfl_sync(0xffffffffu, s[ks][1], src0);
                float v2 = __shfl_sync(0xffffffffu, s[ks][2], src0);
                float v3 = __shfl_sync(0xffffffffu, s[ks][3], src0);
                float w0 = __shfl_sync(0xffffffffu, s[ks][0], src1);
                float w1 = __shfl_sync(0xffffffffu, s[ks][1], src1);
                float w2 = __shfl_sync(0xffffffffu, s[ks][2], src1);
                float w3 = __shfl_sync(0xffffffffu, s[ks][3], src1);
                a[0] = __float_as_uint(odd ? v1 : v0);
                a[1] = __float_as_uint(odd ? v3 : v2);
                a[2] = __float_as_uint(odd ? w1 : w0);
                a[3] = __float_as_uint(odd ? w3 : w2);
            }
#pragma unroll
            for (int nt = 0; nt < 8; nt++) {
                uint32_t b[2];
                b[0] = __float_as_uint(Vs[cur][8 * ks + tig][8 * nt + grp]);
                b[1] = __float_as_uint(Vs[cur][8 * ks + tig + 4][8 * nt + grp]);
                mma_tf32(acc[nt], a, b);
            }
        }
        __syncthreads();
    }

    l0 += __shfl_xor_sync(0xffffffffu, l0, 1);
    l0 += __shfl_xor_sync(0xffffffffu, l0, 2);
    l1 += __shfl_xor_sync(0xffffffffu, l1, 1);
    l1 += __shfl_xor_sync(0xffffffffu, l1, 2);
    const float i0 = 1.f / l0, i1 = 1.f / l1;

    const int tq0 = qb * 64 + wm0 + grp;
    float* o0 = g_O + (size_t)tq0 * DM + h * HD;
    float* o1 = o0 + (size_t)8 * DM;
#pragma unroll
    for (int nt = 0; nt < 8; nt++) {
        const int c  = 8 * nt + 2 * tig;            // logical col within head
        const int p0 = (c & ~15) | perm16(c & 15);
        const int p1 = ((c + 1) & ~15) | perm16((c + 1) & 15);
        o0[p0] = f2tf32(acc[nt][0] * i0);
        o0[p1] = f2tf32(acc[nt][1] * i0);
        o1[p0] = f2tf32(acc[nt][2] * i1);
        o1[p1] = f2tf32(acc[nt][3] * i1);
    }
}

// ---------------------------------------------------------------------------
extern "C" void kernel_launch(void* const* d_in, const int* in_sizes, int n_in,
                              void* d_out, int out_size)
{
    const float* x     = (const float*)d_in[0];
    const float* freqs = (const float*)d_in[1];
    const float* Wq    = (const float*)d_in[3];
    const float* Wk    = (const float*)d_in[4];
    const float* Wv    = (const float*)d_in[5];
    const float* Wo    = (const float*)d_in[6];
    float* out = (float*)d_out;

    // pre-passes: tf32 round + k-perm (+ weight transpose/concat)
    conv_x<<<TT * DM / (256 * 16), 256>>>(x);
    conv_wt<<<dim3(2048 / 32, 64), 256>>>(Wq, 2048, 0);
    conv_wt<<<dim3(512 / 32, 64), 256>>>(Wk, 512, 2048);
    conv_wt<<<dim3(512 / 32, 64), 256>>>(Wv, 512, 2560);
    conv_wt<<<dim3(2048 / 32, 64), 256>>>(Wo, 2048, 3072);

    // fused QKV projections (+RoPE)
    gemm_tc<true><<<dim3(3072 / 128, TT / 128), 256>>>(nullptr, freqs);
    // attention
    attn_tc_kernel<<<dim3(NH, TT / 64), dim3(128)>>>();
    // output projection
    gemm_tc<false><<<dim3(DM / 128, TT / 128), 256>>>(out, nullptr);
}